// round 14
// baseline (speedup 1.0000x reference)
#include <cuda_runtime.h>
#include <cuda_fp16.h>
#include <math.h>
#include <stdint.h>

// ---------------------------------------------------------------------------
// SpatialHead on sm_103a — fp16 mma + ldmatrix(A only), halo-resident 3x3
// convs. B weights pre-packed in mma-fragment order and loaded per-thread via
// LDG: no B smem, no per-chunk barriers (mainloops are barrier-free).
// offset conv + sampling + deform einsum fused (warp-specialized);
// r2 conv + 1x1 conv + sigmoid fused.
// ---------------------------------------------------------------------------

namespace sh {
constexpr int kB = 8, kH = 96, kW = 96;
constexpr int kPos = kB * kH * kW;          // 73728
constexpr float kEps = 1e-5f;
}

// ------------------------- scratch (__device__ globals) --------------------
__device__ __align__(16) __half g_feath[(size_t)sh::kPos * 256];
__device__ __align__(16) __half g_buf0h[sh::kPos * 64];
__device__ __align__(16) __half g_buf1h[sh::kPos * 64];
__device__ __align__(16) float  g_cb[sh::kH * sh::kW * 64];
// weights in mma B-fragment order: [chunk][n8tile][lane] -> uint4
__device__ uint4 g_fw1[72 * 8 * 32];        // coord conv (K=2304 -> 72 chunks)
__device__ uint4 g_fwoff[18 * 4 * 32];      // offset conv (32 outs padded)
__device__ uint4 g_fwdc[18 * 8 * 32];       // deform einsum
__device__ uint4 g_fwr1[18 * 8 * 32];
__device__ uint4 g_fwr2[18 * 8 * 32];
__device__ float g_bnsc[4 * 64];
__device__ float g_bnsh[4 * 64];

// ------------------------------ helpers ------------------------------------
__device__ __forceinline__ unsigned smem_u32(const void* p) {
    unsigned a;
    asm("{ .reg .u64 t; cvta.to.shared.u64 t, %1; cvt.u32.u64 %0, t; }"
        : "=r"(a) : "l"(p));
    return a;
}
__device__ __forceinline__ void cp_async16(unsigned dst, const void* src, bool ok) {
    int sz = ok ? 16 : 0;
    asm volatile("cp.async.cg.shared.global [%0], [%1], 16, %2;\n"
                 :: "r"(dst), "l"(src), "r"(sz));
}
__device__ __forceinline__ void cp_commit() {
    asm volatile("cp.async.commit_group;\n");
}
template <int N>
__device__ __forceinline__ void cp_wait() {
    asm volatile("cp.async.wait_group %0;\n" :: "n"(N));
}
__device__ __forceinline__ void ldsm_x4(uint32_t r[4], unsigned addr) {
    asm volatile("ldmatrix.sync.aligned.m8n8.x4.shared.b16 {%0,%1,%2,%3}, [%4];"
                 : "=r"(r[0]), "=r"(r[1]), "=r"(r[2]), "=r"(r[3]) : "r"(addr));
}
__device__ __forceinline__ void mma_f16(float c[4], const uint32_t a[4],
                                        uint32_t b0, uint32_t b1) {
    asm volatile(
        "mma.sync.aligned.m16n8k16.row.col.f32.f16.f16.f32 "
        "{%0,%1,%2,%3}, {%4,%5,%6,%7}, {%8,%9}, {%0,%1,%2,%3};\n"
        : "+f"(c[0]), "+f"(c[1]), "+f"(c[2]), "+f"(c[3])
        : "r"(a[0]), "r"(a[1]), "r"(a[2]), "r"(a[3]), "r"(b0), "r"(b1));
}
__device__ __forceinline__ void barrier512(int id) {
    asm volatile("bar.sync %0, 512;" :: "r"(id) : "memory");
}
__device__ __forceinline__ uint32_t packh2(float a, float b) {
    __half2 p = __floats2half2_rn(a, b);
    return *(uint32_t*)&p;
}

// ------------------------------ prep kernel --------------------------------
// f2h + fragment-order weight packing + coord bias map + folded BN.
__global__ void prep_kernel(
    const float* __restrict__ features,
    const float* __restrict__ coord_w, const float* __restrict__ coord_b,
    const float* __restrict__ off_w, const float* __restrict__ dc_w,
    const float* __restrict__ r1_w, const float* __restrict__ r2_w,
    const float* __restrict__ bn1g, const float* __restrict__ bn1b,
    const float* __restrict__ bn1m, const float* __restrict__ bn1v,
    const float* __restrict__ bn2g, const float* __restrict__ bn2b,
    const float* __restrict__ bn2m, const float* __restrict__ bn2v,
    const float* __restrict__ bn3g, const float* __restrict__ bn3b,
    const float* __restrict__ bn3m, const float* __restrict__ bn3v,
    const float* __restrict__ bn4g, const float* __restrict__ bn4b,
    const float* __restrict__ bn4m, const float* __restrict__ bn4v)
{
    int idx = blockIdx.x * blockDim.x + threadIdx.x;
    const int NF = sh::kPos * 32;
    const int N2 = sh::kH * sh::kW * 64;
    const int FW1 = 72 * 8 * 32;
    const int FOFF = 18 * 4 * 32;
    const int FSM = 18 * 8 * 32;

    if (idx < NF) {
        const float4* s = (const float4*)features + (size_t)idx * 2;
        float4 v0 = s[0], v1 = s[1];
        uint4 h;
        h.x = packh2(v0.x, v0.y); h.y = packh2(v0.z, v0.w);
        h.z = packh2(v1.x, v1.y); h.w = packh2(v1.z, v1.w);
        *(uint4*)&g_feath[(size_t)idx * 8] = h;
        return;
    }
    idx -= NF;
    if (idx < N2) {
        int o = idx & 63, p = idx >> 6;
        int y = p / 96, x = p % 96;
        float acc = coord_b[o];
        #pragma unroll
        for (int t = 0; t < 9; t++) {
            int yy = y + t / 3 - 1, xx = x + t % 3 - 1;
            if ((unsigned)yy < 96u && (unsigned)xx < 96u) {
                float xv = fmaf((float)xx, 2.0f / 95.0f, -1.0f);
                float yv = fmaf((float)yy, 2.0f / 95.0f, -1.0f);
                acc = fmaf(coord_w[(o * 258 + 256) * 9 + t], xv, acc);
                acc = fmaf(coord_w[(o * 258 + 257) * 9 + t], yv, acc);
            }
        }
        g_cb[p * 64 + o] = acc;
        return;
    }
    idx -= N2;
    if (idx < FW1) {   // coord conv fragments: chg = grp*18 + ch
        int lane = idx & 31, ntg = (idx >> 5) & 7, chg = idx >> 8;
        int grp = chg / 18, ch = chg % 18;
        int g = lane >> 2, tg = lane & 3;
        int o = ntg * 8 + g, t = ch >> 1;
        int cb = grp * 64 + (ch & 1) * 32 + 2 * tg;
        const float* wr = coord_w + (size_t)(o * 258) * 9 + t;
        uint4 v;
        v.x = packh2(wr[(cb + 0) * 9],  wr[(cb + 1) * 9]);
        v.y = packh2(wr[(cb + 8) * 9],  wr[(cb + 9) * 9]);
        v.z = packh2(wr[(cb + 16) * 9], wr[(cb + 17) * 9]);
        v.w = packh2(wr[(cb + 24) * 9], wr[(cb + 25) * 9]);
        g_fw1[idx] = v;
        return;
    }
    idx -= FW1;
    if (idx < FOFF) {   // offset conv fragments (32 outs, o>=18 zero)
        int lane = idx & 31, ntg = (idx >> 5) & 3, ch = idx >> 7;
        int g = lane >> 2, tg = lane & 3;
        int o = ntg * 8 + g, t = ch >> 1;
        int cb = (ch & 1) * 32 + 2 * tg;
        uint4 v = make_uint4(0, 0, 0, 0);
        if (o < 18) {
            const float* wr = off_w + (size_t)(o * 64) * 9 + t;
            v.x = packh2(wr[(cb + 0) * 9],  wr[(cb + 1) * 9]);
            v.y = packh2(wr[(cb + 8) * 9],  wr[(cb + 9) * 9]);
            v.z = packh2(wr[(cb + 16) * 9], wr[(cb + 17) * 9]);
            v.w = packh2(wr[(cb + 24) * 9], wr[(cb + 25) * 9]);
        }
        g_fwoff[idx] = v;
        return;
    }
    idx -= FOFF;
    if (idx < 3 * FSM) {   // dc / r1 / r2 fragments
        int which = idx / FSM;
        int fi = idx % FSM;
        int lane = fi & 31, ntg = (fi >> 5) & 7, ch = fi >> 8;
        int g = lane >> 2, tg = lane & 3;
        int o = ntg * 8 + g, t = ch >> 1;
        int cb = (ch & 1) * 32 + 2 * tg;
        const float* w = (which == 0) ? dc_w : (which == 1) ? r1_w : r2_w;
        const float* wr = w + (size_t)(o * 64) * 9 + t;
        uint4 v;
        v.x = packh2(wr[(cb + 0) * 9],  wr[(cb + 1) * 9]);
        v.y = packh2(wr[(cb + 8) * 9],  wr[(cb + 9) * 9]);
        v.z = packh2(wr[(cb + 16) * 9], wr[(cb + 17) * 9]);
        v.w = packh2(wr[(cb + 24) * 9], wr[(cb + 25) * 9]);
        if (which == 0) g_fwdc[fi] = v;
        else if (which == 1) g_fwr1[fi] = v;
        else g_fwr2[fi] = v;
        return;
    }
    idx -= 3 * FSM;
    if (idx < 512) {
        int which = idx >> 7, r = idx & 127, o = r & 63;
        const float* gs; const float* bs; const float* ms; const float* vs;
        if (which == 0)      { gs = bn1g; bs = bn1b; ms = bn1m; vs = bn1v; }
        else if (which == 1) { gs = bn2g; bs = bn2b; ms = bn2m; vs = bn2v; }
        else if (which == 2) { gs = bn3g; bs = bn3b; ms = bn3m; vs = bn3v; }
        else                 { gs = bn4g; bs = bn4b; ms = bn4m; vs = bn4v; }
        float sc = gs[o] * rsqrtf(vs[o] + sh::kEps);
        if (r < 64) g_bnsc[which * 64 + o] = sc;
        else        g_bnsh[which * 64 + o] = bs[o] - ms[o] * sc;
    }
}

// ------------------- 3x3 conv, halo-resident, barrier-free mainloop --------
// Block: 128 positions (4 rows x 32 cols) x BN cout, 256 threads, 8 warps.
// A via ldmatrix from halo smem; B via LDG.64 from fragment-order gmem.
constexpr int HPITCH = 72;
constexpr int HROWS = 6 * 34;               // 204
constexpr int HBYTES = HROWS * HPITCH * 2;  // 29376

template <int CIN, int BN, int MODE>
__global__ void __launch_bounds__(256, 4)
conv3x3_halo(const __half* __restrict__ in, const uint2* __restrict__ fragB,
             const float* __restrict__ posbias,
             const float* __restrict__ bnsc, const float* __restrict__ bnsh,
             __half* __restrict__ out)
{
    constexpr int NGRP = CIN / 64;
    constexpr int NT = BN / 8;
    constexpr int NBT = BN / 16;             // n8 tiles per warp
    extern __shared__ __half smemh[];
    const unsigned hBase = smem_u32(smemh);

    const int tid = threadIdx.x;
    const int wid = tid >> 5;
    const int lane = tid & 31;
    const int warpM = wid & 3;
    const int warpN = wid >> 2;
    const int g = lane >> 2;
    const int tg = lane & 3;

    const int x0 = blockIdx.x * 32;
    const int ybase = blockIdx.y * 4;
    const int b = blockIdx.z;

    const int lrow = lane & 7;
    const int lsel = lane >> 3;

    unsigned aAddrBase[2];
    #pragma unroll
    for (int mt = 0; mt < 2; mt++) {
        const int p = warpM * 32 + mt * 16 + lrow + ((lsel & 1) << 3);
        const int py = p >> 5, px = p & 31;
        aAddrBase[mt] = hBase
            + (unsigned)(((py + 1) * 34 + (px + 1)) * HPITCH
                         + ((lsel >> 1) << 3)) * 2u;
    }
    const uint2* fwarp = fragB + ((size_t)warpN * NBT) * 64 + lane * 2;

    float c[2][NBT][4];
    #pragma unroll
    for (int mt = 0; mt < 2; mt++)
        #pragma unroll
        for (int nt = 0; nt < NBT; nt++)
            #pragma unroll
            for (int r = 0; r < 4; r++) c[mt][nt][r] = 0.0f;

    for (int grp = 0; grp < NGRP; grp++) {
        if (NGRP > 1 && grp > 0) __syncthreads();   // halo reuse safety
        if (tid < HROWS) {
            const int hr = tid / 34, hc = tid % 34;
            const int yy = ybase - 1 + hr, xx = x0 - 1 + hc;
            const bool ok = ((unsigned)yy < 96u) && ((unsigned)xx < 96u);
            const __half* src = ok
                ? in + (size_t)((b * 96 + yy) * 96 + xx) * CIN + grp * 64
                : in;
            unsigned dst = hBase + (unsigned)(tid * HPITCH) * 2u;
            #pragma unroll
            for (int q = 0; q < 8; q++)
                cp_async16(dst + q * 16, src + q * 8, ok);
        }
        cp_commit();
        cp_wait<0>();
        __syncthreads();

        #pragma unroll 2
        for (int ch = 0; ch < 18; ch++) {
            const int chg = grp * 18 + ch;
            const int t = ch >> 1;
            const int dy = t / 3 - 1, dx = t % 3 - 1;
            const int aoffc = (dy * 34 + dx) * (HPITCH * 2) + (ch & 1) * 64;
            const uint2* fb = fwarp + (size_t)chg * (NT * 64);

            uint2 bq[NBT];
            #pragma unroll
            for (int nt = 0; nt < NBT; nt++) bq[nt] = fb[nt * 64];
            {
                uint32_t a[2][4];
                ldsm_x4(a[0], aAddrBase[0] + aoffc);
                ldsm_x4(a[1], aAddrBase[1] + aoffc);
                #pragma unroll
                for (int nt = 0; nt < NBT; nt++) {
                    mma_f16(c[0][nt], a[0], bq[nt].x, bq[nt].y);
                    mma_f16(c[1][nt], a[1], bq[nt].x, bq[nt].y);
                }
            }
            #pragma unroll
            for (int nt = 0; nt < NBT; nt++) bq[nt] = fb[nt * 64 + 1];
            {
                uint32_t a[2][4];
                ldsm_x4(a[0], aAddrBase[0] + aoffc + 32);
                ldsm_x4(a[1], aAddrBase[1] + aoffc + 32);
                #pragma unroll
                for (int nt = 0; nt < NBT; nt++) {
                    mma_f16(c[0][nt], a[0], bq[nt].x, bq[nt].y);
                    mma_f16(c[1][nt], a[1], bq[nt].x, bq[nt].y);
                }
            }
        }
    }

    #pragma unroll
    for (int mt = 0; mt < 2; mt++) {
        #pragma unroll
        for (int rr = 0; rr < 2; rr++) {
            const int m = warpM * 32 + mt * 16 + rr * 8 + g;
            const int py = ybase + (m >> 5);
            const int px = x0 + (m & 31);
            const size_t pos = ((size_t)b * 96 + py) * 96 + px;
            #pragma unroll
            for (int nt = 0; nt < NBT; nt++) {
                const int o = warpN * (BN / 2) + nt * 8 + tg * 2;
                float v0 = c[mt][nt][rr * 2 + 0];
                float v1 = c[mt][nt][rr * 2 + 1];
                if constexpr (MODE == 0) {
                    const float2 pb = *(const float2*)&posbias[(size_t)(py * 96 + px) * 64 + o];
                    v0 += pb.x; v1 += pb.y;
                }
                const float2 sc = *(const float2*)&bnsc[o];
                const float2 shb = *(const float2*)&bnsh[o];
                v0 = fmaxf(fmaf(v0, sc.x, shb.x), 0.0f);
                v1 = fmaxf(fmaf(v1, sc.y, shb.y), 0.0f);
                *(__half2*)&out[pos * 64 + o] = __floats2half2_rn(v0, v1);
            }
        }
    }
}

// ------ fused offset conv + sampling + deform einsum (warp-specialized) ----
constexpr int BPITCH = 40;                  // A-tile pitch (halves)
constexpr int DA_B = 128 * BPITCH * 2;      // A buffer bytes (10240)
constexpr int ODSMEM = HBYTES;              // phase1 halo (29376) >= 2*DA_B

__global__ void __launch_bounds__(512, 2)
offset_deform(const __half* __restrict__ in, const uint2* __restrict__ foff,
              const float* __restrict__ chbias, const uint2* __restrict__ fdc,
              const float* __restrict__ bnsc, const float* __restrict__ bnsh,
              __half* __restrict__ out)
{
    __shared__ float sOff[128 * 18];
    extern __shared__ __half smemh[];
    const unsigned hBase = smem_u32(smemh);

    const int tid = threadIdx.x;
    const int wid = tid >> 5;
    const int lane = tid & 31;

    const int x0 = blockIdx.x * 32;
    const int ybase = blockIdx.y * 4;
    const int b = blockIdx.z;

    const int lrow = lane & 7;
    const int lsel = lane >> 3;

    // ===================== phase 1: offset conv (warps 0-7) ================
    {
        // halo load (all 512 threads participate in sync)
        if (tid < HROWS) {
            const int hr = tid / 34, hc = tid % 34;
            const int yy = ybase - 1 + hr, xx = x0 - 1 + hc;
            const bool ok = ((unsigned)yy < 96u) && ((unsigned)xx < 96u);
            const __half* src = ok
                ? in + (size_t)((b * 96 + yy) * 96 + xx) * 64
                : in;
            unsigned dst = hBase + (unsigned)(tid * HPITCH) * 2u;
            #pragma unroll
            for (int q = 0; q < 8; q++)
                cp_async16(dst + q * 16, src + q * 8, ok);
        }
        cp_commit();
        cp_wait<0>();
        __syncthreads();

        if (wid < 8) {
            const int warpM = wid & 3;
            const int warpN = (wid >> 2) & 1;
            const int g = lane >> 2;
            const int tg = lane & 3;

            unsigned aAddrBase[2];
            #pragma unroll
            for (int mt = 0; mt < 2; mt++) {
                const int p = warpM * 32 + mt * 16 + lrow + ((lsel & 1) << 3);
                const int py = p >> 5, px = p & 31;
                aAddrBase[mt] = hBase
                    + (unsigned)(((py + 1) * 34 + (px + 1)) * HPITCH
                                 + ((lsel >> 1) << 3)) * 2u;
            }
            const uint2* fwarp = foff + ((size_t)warpN * 2) * 64 + lane * 2;

            float c[2][2][4];
            #pragma unroll
            for (int mt = 0; mt < 2; mt++)
                #pragma unroll
                for (int nt = 0; nt < 2; nt++)
                    #pragma unroll
                    for (int r = 0; r < 4; r++) c[mt][nt][r] = 0.0f;

            #pragma unroll 2
            for (int ch = 0; ch < 18; ch++) {
                const int t = ch >> 1;
                const int dy = t / 3 - 1, dx = t % 3 - 1;
                const int aoffc = (dy * 34 + dx) * (HPITCH * 2) + (ch & 1) * 64;
                const uint2* fb = fwarp + (size_t)ch * (4 * 64);

                uint2 bq[2];
                bq[0] = fb[0]; bq[1] = fb[64];
                {
                    uint32_t a[2][4];
                    ldsm_x4(a[0], aAddrBase[0] + aoffc);
                    ldsm_x4(a[1], aAddrBase[1] + aoffc);
                    #pragma unroll
                    for (int nt = 0; nt < 2; nt++) {
                        mma_f16(c[0][nt], a[0], bq[nt].x, bq[nt].y);
                        mma_f16(c[1][nt], a[1], bq[nt].x, bq[nt].y);
                    }
                }
                bq[0] = fb[1]; bq[1] = fb[65];
                {
                    uint32_t a[2][4];
                    ldsm_x4(a[0], aAddrBase[0] + aoffc + 32);
                    ldsm_x4(a[1], aAddrBase[1] + aoffc + 32);
                    #pragma unroll
                    for (int nt = 0; nt < 2; nt++) {
                        mma_f16(c[0][nt], a[0], bq[nt].x, bq[nt].y);
                        mma_f16(c[1][nt], a[1], bq[nt].x, bq[nt].y);
                    }
                }
            }

            #pragma unroll
            for (int mt = 0; mt < 2; mt++)
                #pragma unroll
                for (int rr = 0; rr < 2; rr++) {
                    const int m = warpM * 32 + mt * 16 + rr * 8 + g;
                    #pragma unroll
                    for (int nt = 0; nt < 2; nt++) {
                        const int o = warpN * 16 + nt * 8 + tg * 2;
                        if (o < 18)
                            sOff[m * 18 + o] = c[mt][nt][rr * 2 + 0] + chbias[o];
                        if (o + 1 < 18)
                            sOff[m * 18 + o + 1] = c[mt][nt][rr * 2 + 1] + chbias[o + 1];
                    }
                }
        }
        __syncthreads();
    }

    // ===================== phase 2: producer / consumer =====================
    const unsigned aBuf = hBase;                 // 2 x DA_B (overlays halo)

    if (wid < 8) {
        // ---------------- producers: sample chunk ch -> A buf ch%2 ---------
        const int sp = tid >> 1;
        const int sub = (tid & 1) * 16;
        const int py = ybase + (sp >> 5), px = x0 + (sp & 31);
        const __half* img = in + (size_t)b * (96 * 96 * 64);
        __half* dstBase = smemh + sp * BPITCH + sub;

        #pragma unroll 1
        for (int ch = 0; ch < 18; ch++) {
            const int t = ch >> 1;
            const int c0 = (ch & 1) * 32 + sub;
            const float oy = sOff[sp * 18 + 2 * t];
            const float ox = sOff[sp * 18 + 2 * t + 1];
            const float pyf = (float)(py + t / 3 - 1) + oy;
            const float pxf = (float)(px + t % 3 - 1) + ox;
            const float y0f = floorf(pyf), x0f = floorf(pxf);
            const float fy = pyf - y0f, fx = pxf - x0f;
            const int iy = (int)y0f, ix = (int)x0f;
            const bool vy0 = (unsigned)iy < 96u, vy1 = (unsigned)(iy + 1) < 96u;
            const bool vx0 = (unsigned)ix < 96u, vx1 = (unsigned)(ix + 1) < 96u;
            const float w00 = (vy0 && vx0) ? (1.0f - fy) * (1.0f - fx) : 0.0f;
            const float w01 = (vy0 && vx1) ? (1.0f - fy) * fx : 0.0f;
            const float w10 = (vy1 && vx0) ? fy * (1.0f - fx) : 0.0f;
            const float w11 = (vy1 && vx1) ? fy * fx : 0.0f;
            const int iy0 = min(max(iy, 0), 95), iy1 = min(max(iy + 1, 0), 95);
            const int ix0 = min(max(ix, 0), 95), ix1 = min(max(ix + 1, 0), 95);

            float2 acc[8];
            #pragma unroll
            for (int i = 0; i < 8; i++) acc[i] = make_float2(0.f, 0.f);

            auto pair = [&](int ya, int xa, float wa, int yb, int xb, float wb) {
                const uint4* pa = (const uint4*)(img + (size_t)(ya * 96 + xa) * 64 + c0);
                const uint4* pb = (const uint4*)(img + (size_t)(yb * 96 + xb) * 64 + c0);
                uint4 a0 = pa[0], a1 = pa[1], b0 = pb[0], b1 = pb[1];
                const __half2* ha0 = (const __half2*)&a0;
                const __half2* ha1 = (const __half2*)&a1;
                const __half2* hb0 = (const __half2*)&b0;
                const __half2* hb1 = (const __half2*)&b1;
                #pragma unroll
                for (int i = 0; i < 4; i++) {
                    float2 f = __half22float2(ha0[i]);
                    acc[i].x = fmaf(wa, f.x, acc[i].x);
                    acc[i].y = fmaf(wa, f.y, acc[i].y);
                    f = __half22float2(ha1[i]);
                    acc[4 + i].x = fmaf(wa, f.x, acc[4 + i].x);
                    acc[4 + i].y = fmaf(wa, f.y, acc[4 + i].y);
                    f = __half22float2(hb0[i]);
                    acc[i].x = fmaf(wb, f.x, acc[i].x);
                    acc[i].y = fmaf(wb, f.y, acc[i].y);
                    f = __half22float2(hb1[i]);
                    acc[4 + i].x = fmaf(wb, f.x, acc[4 + i].x);
                    acc[4 + i].y = fmaf(wb, f.y, acc[4 + i].y);
                }
            };
            pair(iy0, ix0, w00, iy0, ix1, w01);
            pair(iy1, ix0, w10, iy1, ix1, w11);

            __half2 r[8];
            #pragma unroll
            for (int i = 0; i < 8; i++)
                r[i] = __floats2half2_rn(acc[i].x, acc[i].y);
            __half* dst = dstBase + (ch & 1) * (DA_B / 2);
            *(uint4*)dst = ((uint4*)r)[0];
            *(uint4*)(dst + 8) = ((uint4*)r)[1];

            barrier512(1 + (ch & 1));
        }
    } else {
        // ---------------- consumers: mma chunk ch from A buf ch%2 ----------
        const int cw = wid - 8;
        const int warpM = cw & 3;
        const int warpN = cw >> 2;
        const int g = lane >> 2;
        const int tg = lane & 3;

        const int aoff = (warpM * 32 + lrow + ((lsel & 1) << 3)) * BPITCH
                       + ((lsel >> 1) << 3);
        const uint2* fwarp = fdc + ((size_t)warpN * 4) * 64 + lane * 2;

        float c[2][4][4];
        #pragma unroll
        for (int mt = 0; mt < 2; mt++)
            #pragma unroll
            for (int nt = 0; nt < 4; nt++)
                #pragma unroll
                for (int r = 0; r < 4; r++) c[mt][nt][r] = 0.0f;

        #pragma unroll 1
        for (int ch = 0; ch < 18; ch++) {
            const uint2* fb = fwarp + (size_t)ch * (8 * 64);
            uint2 bq0[4], bq1[4];
            #pragma unroll
            for (int nt = 0; nt < 4; nt++) {
                bq0[nt] = fb[nt * 64];
                bq1[nt] = fb[nt * 64 + 1];
            }

            barrier512(1 + (ch & 1));

            const unsigned aAddr = aBuf + (unsigned)((ch & 1) * DA_B)
                                 + (unsigned)aoff * 2u;
            {
                uint32_t a[2][4];
                ldsm_x4(a[0], aAddr);
                ldsm_x4(a[1], aAddr + 16 * BPITCH * 2);
                #pragma unroll
                for (int nt = 0; nt < 4; nt++) {
                    mma_f16(c[0][nt], a[0], bq0[nt].x, bq0[nt].y);
                    mma_f16(c[1][nt], a[1], bq0[nt].x, bq0[nt].y);
                }
            }
            {
                uint32_t a[2][4];
                ldsm_x4(a[0], aAddr + 32);
                ldsm_x4(a[1], aAddr + 16 * BPITCH * 2 + 32);
                #pragma unroll
                for (int nt = 0; nt < 4; nt++) {
                    mma_f16(c[0][nt], a[0], bq1[nt].x, bq1[nt].y);
                    mma_f16(c[1][nt], a[1], bq1[nt].x, bq1[nt].y);
                }
            }
        }

        #pragma unroll
        for (int mt = 0; mt < 2; mt++) {
            #pragma unroll
            for (int rr = 0; rr < 2; rr++) {
                const int m = warpM * 32 + mt * 16 + rr * 8 + g;
                const int py = ybase + (m >> 5);
                const int px = x0 + (m & 31);
                const size_t pos = ((size_t)b * 96 + py) * 96 + px;
                #pragma unroll
                for (int nt = 0; nt < 4; nt++) {
                    const int o = warpN * 32 + nt * 8 + tg * 2;
                    float v0 = c[mt][nt][rr * 2 + 0];
                    float v1 = c[mt][nt][rr * 2 + 1];
                    const float2 sc = *(const float2*)&bnsc[o];
                    const float2 shb = *(const float2*)&bnsh[o];
                    v0 = fmaxf(fmaf(v0, sc.x, shb.x), 0.0f);
                    v1 = fmaxf(fmaf(v1, sc.y, shb.y), 0.0f);
                    *(__half2*)&out[pos * 64 + o] = __floats2half2_rn(v0, v1);
                }
            }
        }
    }
}

// ---------------- fused r2 conv + BN4 + ReLU + 1x1 conv + sigmoid ----------
__global__ void __launch_bounds__(256, 4)
r2_final(const __half* __restrict__ in, const uint2* __restrict__ fragB,
         const float* __restrict__ bnsc, const float* __restrict__ bnsh,
         const float* __restrict__ ow, const float* __restrict__ ob,
         float* __restrict__ out)
{
    __shared__ float sRed[2][128];
    extern __shared__ __half smemh[];
    const unsigned hBase = smem_u32(smemh);

    const int tid = threadIdx.x;
    const int wid = tid >> 5;
    const int lane = tid & 31;
    const int warpM = wid & 3;
    const int warpN = wid >> 2;
    const int g = lane >> 2;
    const int tg = lane & 3;

    const int x0 = blockIdx.x * 32;
    const int ybase = blockIdx.y * 4;
    const int b = blockIdx.z;

    const int lrow = lane & 7;
    const int lsel = lane >> 3;

    unsigned aAddrBase[2];
    #pragma unroll
    for (int mt = 0; mt < 2; mt++) {
        const int p = warpM * 32 + mt * 16 + lrow + ((lsel & 1) << 3);
        const int py = p >> 5, px = p & 31;
        aAddrBase[mt] = hBase
            + (unsigned)(((py + 1) * 34 + (px + 1)) * HPITCH
                         + ((lsel >> 1) << 3)) * 2u;
    }
    const uint2* fwarp = fragB + ((size_t)warpN * 4) * 64 + lane * 2;

    float c[2][4][4];
    #pragma unroll
    for (int mt = 0; mt < 2; mt++)
        #pragma unroll
        for (int nt = 0; nt < 4; nt++)
            #pragma unroll
            for (int r = 0; r < 4; r++) c[mt][nt][r] = 0.0f;

    if (tid < HROWS) {
        const int hr = tid / 34, hc = tid % 34;
        const int yy = ybase - 1 + hr, xx = x0 - 1 + hc;
        const bool ok = ((unsigned)yy < 96u) && ((unsigned)xx < 96u);
        const __half* src = ok
            ? in + (size_t)((b * 96 + yy) * 96 + xx) * 64
            : in;
        unsigned dst = hBase + (unsigned)(tid * HPITCH) * 2u;
        #pragma unroll
        for (int q = 0; q < 8; q++)
            cp_async16(dst + q * 16, src + q * 8, ok);
    }
    cp_commit();
    cp_wait<0>();
    __syncthreads();

    #pragma unroll 2
    for (int ch = 0; ch < 18; ch++) {
        const int t = ch >> 1;
        const int dy = t / 3 - 1, dx = t % 3 - 1;
        const int aoffc = (dy * 34 + dx) * (HPITCH * 2) + (ch & 1) * 64;
        const uint2* fb = fwarp + (size_t)ch * (8 * 64);

        uint2 bq[4];
        #pragma unroll
        for (int nt = 0; nt < 4; nt++) bq[nt] = fb[nt * 64];
        {
            uint32_t a[2][4];
            ldsm_x4(a[0], aAddrBase[0] + aoffc);
            ldsm_x4(a[1], aAddrBase[1] + aoffc);
            #pragma unroll
            for (int nt = 0; nt < 4; nt++) {
                mma_f16(c[0][nt], a[0], bq[nt].x, bq[nt].y);
                mma_f16(c[1][nt], a[1], bq[nt].x, bq[nt].y);
            }
        }
        #pragma unroll
        for (int nt = 0; nt < 4; nt++) bq[nt] = fb[nt * 64 + 1];
        {
            uint32_t a[2][4];
            ldsm_x4(a[0], aAddrBase[0] + aoffc + 32);
            ldsm_x4(a[1], aAddrBase[1] + aoffc + 32);
            #pragma unroll
            for (int nt = 0; nt < 4; nt++) {
                mma_f16(c[0][nt], a[0], bq[nt].x, bq[nt].y);
                mma_f16(c[1][nt], a[1], bq[nt].x, bq[nt].y);
            }
        }
    }

    float part[4] = {0.f, 0.f, 0.f, 0.f};
    #pragma unroll
    for (int mt = 0; mt < 2; mt++) {
        #pragma unroll
        for (int rr = 0; rr < 2; rr++) {
            #pragma unroll
            for (int nt = 0; nt < 4; nt++) {
                const int o = warpN * 32 + nt * 8 + tg * 2;
                const float2 sc = *(const float2*)&bnsc[o];
                const float2 shb = *(const float2*)&bnsh[o];
                float v0 = fmaxf(fmaf(c[mt][nt][rr * 2 + 0], sc.x, shb.x), 0.0f);
                float v1 = fmaxf(fmaf(c[mt][nt][rr * 2 + 1], sc.y, shb.y), 0.0f);
                part[mt * 2 + rr] = fmaf(v0, ow[o],
                                    fmaf(v1, ow[o + 1], part[mt * 2 + rr]));
            }
        }
    }
    #pragma unroll
    for (int i = 0; i < 4; i++) {
        part[i] += __shfl_xor_sync(0xffffffffu, part[i], 1);
        part[i] += __shfl_xor_sync(0xffffffffu, part[i], 2);
    }
    if (tg == 0) {
        #pragma unroll
        for (int i = 0; i < 4; i++) {
            const int m = warpM * 32 + (i >> 1) * 16 + (i & 1) * 8 + g;
            sRed[warpN][m] = part[i];
        }
    }
    __syncthreads();
    if (tid < 128) {
        const int py = ybase + (tid >> 5);
        const int px = x0 + (tid & 31);
        const float s = sRed[0][tid] + sRed[1][tid] + ob[0];
        out[((size_t)b * 96 + py) * 96 + px] = 1.0f / (1.0f + expf(-s));
    }
}

// ------------------------------ launcher -----------------------------------
extern "C" void kernel_launch(void* const* d_in, const int* in_sizes, int n_in,
                              void* d_out, int out_size)
{
    const float* features = (const float*)d_in[0];
    const float* coord_w  = (const float*)d_in[1];
    const float* coord_b  = (const float*)d_in[2];
    const float* bn1g = (const float*)d_in[3];
    const float* bn1b = (const float*)d_in[4];
    const float* bn1m = (const float*)d_in[5];
    const float* bn1v = (const float*)d_in[6];
    const float* off_w = (const float*)d_in[7];
    const float* off_b = (const float*)d_in[8];
    const float* dc_w  = (const float*)d_in[9];
    const float* bn2g = (const float*)d_in[10];
    const float* bn2b = (const float*)d_in[11];
    const float* bn2m = (const float*)d_in[12];
    const float* bn2v = (const float*)d_in[13];
    const float* r1_w = (const float*)d_in[14];
    const float* bn3g = (const float*)d_in[15];
    const float* bn3b = (const float*)d_in[16];
    const float* bn3m = (const float*)d_in[17];
    const float* bn3v = (const float*)d_in[18];
    const float* r2_w = (const float*)d_in[19];
    const float* bn4g = (const float*)d_in[20];
    const float* bn4b = (const float*)d_in[21];
    const float* bn4m = (const float*)d_in[22];
    const float* bn4v = (const float*)d_in[23];
    const float* out_w = (const float*)d_in[24];
    const float* out_b = (const float*)d_in[25];

    __half *p_feath, *p_buf0, *p_buf1;
    float *p_cb, *p_bnsc, *p_bnsh;
    uint2 *p_fw1, *p_foff, *p_fdc, *p_fr1, *p_fr2;
    cudaGetSymbolAddress((void**)&p_feath, g_feath);
    cudaGetSymbolAddress((void**)&p_buf0, g_buf0h);
    cudaGetSymbolAddress((void**)&p_buf1, g_buf1h);
    cudaGetSymbolAddress((void**)&p_cb,   g_cb);
    cudaGetSymbolAddress((void**)&p_fw1,  g_fw1);
    cudaGetSymbolAddress((void**)&p_foff, g_fwoff);
    cudaGetSymbolAddress((void**)&p_fdc,  g_fwdc);
    cudaGetSymbolAddress((void**)&p_fr1,  g_fwr1);
    cudaGetSymbolAddress((void**)&p_fr2,  g_fwr2);
    cudaGetSymbolAddress((void**)&p_bnsc, g_bnsc);
    cudaGetSymbolAddress((void**)&p_bnsh, g_bnsh);

    cudaFuncSetAttribute(conv3x3_halo<256, 64, 0>,
                         cudaFuncAttributeMaxDynamicSharedMemorySize, HBYTES);
    cudaFuncSetAttribute(conv3x3_halo<64, 64, 2>,
                         cudaFuncAttributeMaxDynamicSharedMemorySize, HBYTES);
    cudaFuncSetAttribute(offset_deform,
                         cudaFuncAttributeMaxDynamicSharedMemorySize, ODSMEM);
    cudaFuncSetAttribute(r2_final,
                         cudaFuncAttributeMaxDynamicSharedMemorySize, HBYTES);

    // 1. prep: f2h + fragment packing + coord bias map + folded BN
    const int prep_total = sh::kPos * 32 + 96 * 96 * 64
                         + 72 * 8 * 32 + 18 * 4 * 32 + 3 * 18 * 8 * 32 + 512;
    prep_kernel<<<(prep_total + 255) / 256, 256>>>(
        features, coord_w, coord_b, off_w, dc_w, r1_w, r2_w,
        bn1g, bn1b, bn1m, bn1v, bn2g, bn2b, bn2m, bn2v,
        bn3g, bn3b, bn3m, bn3v, bn4g, bn4b, bn4m, bn4v);

    dim3 grid(3, 24, 8);   // 32 x-cols, 4 rows -> 128 positions per block

    // 2. coord conv (256->64, 4 halo groups) + coord bias + BN1 + ReLU
    conv3x3_halo<256, 64, 0><<<grid, 256, HBYTES>>>(
        p_feath, p_fw1, p_cb, p_bnsc + 0, p_bnsh + 0, p_buf0);

    // 3. offset conv + sampling + deform einsum + BN2 + ReLU -> buf1
    offset_deform<<<grid, 512, ODSMEM>>>(
        p_buf0, p_foff, off_b, p_fdc, p_bnsc + 64, p_bnsh + 64, p_buf1);

    // 4. r1 conv + BN3 + ReLU -> buf0
    conv3x3_halo<64, 64, 2><<<grid, 256, HBYTES>>>(
        p_buf1, p_fr1, nullptr, p_bnsc + 128, p_bnsh + 128, p_buf0);

    // 5. r2 conv + BN4 + ReLU + 1x1 conv + sigmoid -> d_out
    r2_final<<<grid, 256, HBYTES>>>(
        p_buf0, p_fr2, p_bnsc + 192, p_bnsh + 192, out_w, out_b,
        (float*)d_out);
}

// round 15
// speedup vs baseline: 1.0071x; 1.0071x over previous
#include <cuda_runtime.h>
#include <cuda_fp16.h>
#include <math.h>
#include <stdint.h>

// ---------------------------------------------------------------------------
// SpatialHead on sm_103a — fp16 mma + ldmatrix, halo-resident 3x3 convs
// (R12 structure). Coord conv reads fp32 features directly (cvt in halo
// fill) — no f2h pre-pass. offset conv + sampling fused; r2 + 1x1 fused.
// ---------------------------------------------------------------------------

namespace sh {
constexpr int kB = 8, kH = 96, kW = 96;
constexpr int kPos = kB * kH * kW;          // 73728
constexpr float kEps = 1e-5f;
}

// ------------------------- scratch (__device__ globals) --------------------
__device__ __align__(16) __half g_buf0h[sh::kPos * 64];
__device__ __align__(16) __half g_buf1h[sh::kPos * 64];
__device__ __align__(16) __half g_samph[(size_t)sh::kPos * 576];
__device__ __align__(16) __half g_w1h[64 * 2304];                 // [o][k]
__device__ __align__(16) __half g_woffh[32 * 576];
__device__ __align__(16) __half g_wdch[64 * 576];
__device__ __align__(16) __half g_wr1h[64 * 576];
__device__ __align__(16) __half g_wr2h[64 * 576];
__device__ __align__(16) float  g_cb[sh::kH * sh::kW * 64];
__device__ float g_bnsc[4 * 64];
__device__ float g_bnsh[4 * 64];

// ------------------------------ helpers ------------------------------------
__device__ __forceinline__ unsigned smem_u32(const void* p) {
    unsigned a;
    asm("{ .reg .u64 t; cvta.to.shared.u64 t, %1; cvt.u32.u64 %0, t; }"
        : "=r"(a) : "l"(p));
    return a;
}
__device__ __forceinline__ void cp_async16(unsigned dst, const void* src, bool ok) {
    int sz = ok ? 16 : 0;
    asm volatile("cp.async.cg.shared.global [%0], [%1], 16, %2;\n"
                 :: "r"(dst), "l"(src), "r"(sz));
}
__device__ __forceinline__ void cp_commit() {
    asm volatile("cp.async.commit_group;\n");
}
template <int N>
__device__ __forceinline__ void cp_wait() {
    asm volatile("cp.async.wait_group %0;\n" :: "n"(N));
}
__device__ __forceinline__ void ldsm_x4(uint32_t r[4], unsigned addr) {
    asm volatile("ldmatrix.sync.aligned.m8n8.x4.shared.b16 {%0,%1,%2,%3}, [%4];"
                 : "=r"(r[0]), "=r"(r[1]), "=r"(r[2]), "=r"(r[3]) : "r"(addr));
}
__device__ __forceinline__ void mma_f16(float c[4], const uint32_t a[4],
                                        uint32_t b0, uint32_t b1) {
    asm volatile(
        "mma.sync.aligned.m16n8k16.row.col.f32.f16.f16.f32 "
        "{%0,%1,%2,%3}, {%4,%5,%6,%7}, {%8,%9}, {%0,%1,%2,%3};\n"
        : "+f"(c[0]), "+f"(c[1]), "+f"(c[2]), "+f"(c[3])
        : "r"(a[0]), "r"(a[1]), "r"(a[2]), "r"(a[3]), "r"(b0), "r"(b1));
}
__device__ __forceinline__ uint32_t packh2(float a, float b) {
    __half2 p = __floats2half2_rn(a, b);
    return *(uint32_t*)&p;
}

// ------------------------------ prep kernel --------------------------------
__global__ void prep_kernel(
    const float* __restrict__ coord_w, const float* __restrict__ coord_b,
    const float* __restrict__ off_w, const float* __restrict__ dc_w,
    const float* __restrict__ r1_w, const float* __restrict__ r2_w,
    const float* __restrict__ bn1g, const float* __restrict__ bn1b,
    const float* __restrict__ bn1m, const float* __restrict__ bn1v,
    const float* __restrict__ bn2g, const float* __restrict__ bn2b,
    const float* __restrict__ bn2m, const float* __restrict__ bn2v,
    const float* __restrict__ bn3g, const float* __restrict__ bn3b,
    const float* __restrict__ bn3m, const float* __restrict__ bn3v,
    const float* __restrict__ bn4g, const float* __restrict__ bn4b,
    const float* __restrict__ bn4m, const float* __restrict__ bn4v)
{
    int idx = blockIdx.x * blockDim.x + threadIdx.x;
    const int N1 = 64 * 2304;
    const int N2 = sh::kH * sh::kW * 64;
    const int NOFF = 32 * 576;
    const int N3 = 64 * 576;

    if (idx < N1) {
        int o = idx / 2304, k = idx % 2304;
        int t = k >> 8, c = k & 255;
        g_w1h[idx] = __float2half(coord_w[(o * 258 + c) * 9 + t]);
        return;
    }
    idx -= N1;
    if (idx < N2) {
        int o = idx & 63, p = idx >> 6;
        int y = p / 96, x = p % 96;
        float acc = coord_b[o];
        #pragma unroll
        for (int t = 0; t < 9; t++) {
            int yy = y + t / 3 - 1, xx = x + t % 3 - 1;
            if ((unsigned)yy < 96u && (unsigned)xx < 96u) {
                float xv = fmaf((float)xx, 2.0f / 95.0f, -1.0f);
                float yv = fmaf((float)yy, 2.0f / 95.0f, -1.0f);
                acc = fmaf(coord_w[(o * 258 + 256) * 9 + t], xv, acc);
                acc = fmaf(coord_w[(o * 258 + 257) * 9 + t], yv, acc);
            }
        }
        g_cb[p * 64 + o] = acc;
        return;
    }
    idx -= N2;
    if (idx < NOFF) {
        int o = idx / 576, k = idx % 576;
        int t = k >> 6, c = k & 63;
        g_woffh[idx] = (o < 18) ? __float2half(off_w[(o * 64 + c) * 9 + t])
                                : __float2half(0.0f);
        return;
    }
    idx -= NOFF;
    if (idx < N3) {
        int o = idx / 576, k = idx % 576;
        int t = k >> 6, c = k & 63;
        g_wdch[idx] = __float2half(dc_w[(o * 64 + c) * 9 + t]);
        return;
    }
    idx -= N3;
    if (idx < N3) {
        int o = idx / 576, k = idx % 576;
        int t = k >> 6, c = k & 63;
        g_wr1h[idx] = __float2half(r1_w[(o * 64 + c) * 9 + t]);
        return;
    }
    idx -= N3;
    if (idx < N3) {
        int o = idx / 576, k = idx % 576;
        int t = k >> 6, c = k & 63;
        g_wr2h[idx] = __float2half(r2_w[(o * 64 + c) * 9 + t]);
        return;
    }
    idx -= N3;
    if (idx < 512) {
        int which = idx >> 7, r = idx & 127, o = r & 63;
        const float* gs; const float* bs; const float* ms; const float* vs;
        if (which == 0)      { gs = bn1g; bs = bn1b; ms = bn1m; vs = bn1v; }
        else if (which == 1) { gs = bn2g; bs = bn2b; ms = bn2m; vs = bn2v; }
        else if (which == 2) { gs = bn3g; bs = bn3b; ms = bn3m; vs = bn3v; }
        else                 { gs = bn4g; bs = bn4b; ms = bn4m; vs = bn4v; }
        float sc = gs[o] * rsqrtf(vs[o] + sh::kEps);
        if (r < 64) g_bnsc[which * 64 + o] = sc;
        else        g_bnsh[which * 64 + o] = bs[o] - ms[o] * sc;
    }
}

// ------------------- 3x3 conv with smem-resident halo tile -----------------
// Block: 128 positions (4 rows x 32 cols) x BN cout, 256 threads, 8 warps.
// F32IN: input is fp32, halo fill converts to fp16 in-register (coord conv);
// otherwise halo streams via cp.async from fp16 input.
// MODE 0: + per-position bias + BN + ReLU; MODE 2: BN + ReLU.
constexpr int HPITCH = 72;                  // halves per halo position
constexpr int HROWS = 6 * 34;               // 204
constexpr int HBYTES = HROWS * HPITCH * 2;  // 29376
constexpr int BPITCH = 40;                  // halves per weight row

template <bool F32IN, int CIN, int BN, int MODE>
__global__ void __launch_bounds__(256, 4)
conv3x3_halo(const void* __restrict__ in_, const __half* __restrict__ wT,
             const float* __restrict__ posbias,
             const float* __restrict__ bnsc, const float* __restrict__ bnsh,
             __half* __restrict__ out)
{
    constexpr int NGRP = CIN / 64;
    constexpr int KTOT = 9 * CIN;
    constexpr int BSTG = BN * BPITCH;
    constexpr int NWARP = BN / 2;
    constexpr int NBT = NWARP / 8;
    extern __shared__ __half smemh[];
    const unsigned hBase = smem_u32(smemh);
    const unsigned bBase = hBase + HBYTES;

    const __half* inh = (const __half*)in_;
    const float* inf = (const float*)in_;

    const int tid = threadIdx.x;
    const int wid = tid >> 5;
    const int lane = tid & 31;
    const int warpM = wid & 3;
    const int warpN = wid >> 2;
    const int g = lane >> 2;
    const int tg = lane & 3;

    const int x0 = blockIdx.x * 32;
    const int ybase = blockIdx.y * 4;
    const int b = blockIdx.z;

    const int lrow = lane & 7;
    const int lsel = lane >> 3;

    unsigned aAddrBase[2];
    #pragma unroll
    for (int mt = 0; mt < 2; mt++) {
        const int p = warpM * 32 + mt * 16 + lrow + ((lsel & 1) << 3);
        const int py = p >> 5, px = p & 31;
        aAddrBase[mt] = hBase
            + (unsigned)(((py + 1) * 34 + (px + 1)) * HPITCH
                         + ((lsel >> 1) << 3)) * 2u;
    }
    const int boff = (warpN * NWARP + lrow + ((lsel >> 1) << 3)) * BPITCH
                   + ((lsel & 1) << 3);

    float c[2][NBT][4];
    #pragma unroll
    for (int mt = 0; mt < 2; mt++)
        #pragma unroll
        for (int nt = 0; nt < NBT; nt++)
            #pragma unroll
            for (int r = 0; r < 4; r++) c[mt][nt][r] = 0.0f;

    auto prefetchB = [&](int grp, int ch, int buf) {
        if (tid < BN * 4) {
            const int o = tid >> 2;
            const int q = tid & 3;
            const int koff = (ch >> 1) * CIN + grp * 64 + (ch & 1) * 32;
            const __half* ws = wT + (size_t)o * KTOT + koff + q * 8;
            unsigned dstB = bBase + (unsigned)(buf * BSTG + o * BPITCH) * 2u
                          + q * 16u;
            cp_async16(dstB, ws, true);
        }
    };

    for (int grp = 0; grp < NGRP; grp++) {
        __syncthreads();
        if constexpr (F32IN) {
            // fp32 -> fp16 conversion in halo fill: 408 half-rows of 32 ch
            for (int j = tid; j < HROWS * 2; j += 256) {
                const int r = j >> 1;
                const int h = (j & 1) * 32;
                const int hr = r / 34, hc = r % 34;
                const int yy = ybase - 1 + hr, xx = x0 - 1 + hc;
                uint4 pk[4];
                if ((unsigned)yy < 96u && (unsigned)xx < 96u) {
                    const float4* src = (const float4*)(inf
                        + (size_t)((b * 96 + yy) * 96 + xx) * CIN + grp * 64 + h);
                    #pragma unroll
                    for (int q = 0; q < 4; q++) {
                        float4 a = src[2 * q], d = src[2 * q + 1];
                        pk[q].x = packh2(a.x, a.y);
                        pk[q].y = packh2(a.z, a.w);
                        pk[q].z = packh2(d.x, d.y);
                        pk[q].w = packh2(d.z, d.w);
                    }
                } else {
                    #pragma unroll
                    for (int q = 0; q < 4; q++) pk[q] = make_uint4(0, 0, 0, 0);
                }
                uint4* dst = (uint4*)(smemh + r * HPITCH + h);
                dst[0] = pk[0]; dst[1] = pk[1]; dst[2] = pk[2]; dst[3] = pk[3];
            }
        } else {
            if (tid < HROWS) {
                const int hr = tid / 34, hc = tid % 34;
                const int yy = ybase - 1 + hr, xx = x0 - 1 + hc;
                const bool ok = ((unsigned)yy < 96u) && ((unsigned)xx < 96u);
                const __half* src = ok
                    ? inh + (size_t)((b * 96 + yy) * 96 + xx) * CIN + grp * 64
                    : inh;
                unsigned dst = hBase + (unsigned)(tid * HPITCH) * 2u;
                #pragma unroll
                for (int q = 0; q < 8; q++)
                    cp_async16(dst + q * 16, src + q * 8, ok);
            }
            cp_commit();
        }
        prefetchB(grp, 0, 0); cp_commit();
        prefetchB(grp, 1, 1); cp_commit();

        #pragma unroll
        for (int ch = 0; ch < 18; ch++) {
            cp_wait<1>();
            __syncthreads();
            if (ch + 2 < 18) prefetchB(grp, ch + 2, (ch + 2) % 3);
            cp_commit();

            const int t = ch >> 1;
            const int dy = t / 3 - 1, dx = t % 3 - 1;
            const int aoffc = (dy * 34 + dx) * (HPITCH * 2) + (ch & 1) * 64;
            const unsigned bAddr = bBase
                + (unsigned)((ch % 3) * BSTG + boff) * 2u;

            #pragma unroll
            for (int ks = 0; ks < 2; ks++) {
                uint32_t a[2][4], bb[NBT / 2][4];
                ldsm_x4(a[0], aAddrBase[0] + aoffc + ks * 32);
                ldsm_x4(a[1], aAddrBase[1] + aoffc + ks * 32);
                #pragma unroll
                for (int p = 0; p < NBT / 2; p++)
                    ldsm_x4(bb[p], bAddr + p * 16 * BPITCH * 2 + ks * 32);
                #pragma unroll
                for (int p = 0; p < NBT / 2; p++)
                    #pragma unroll
                    for (int q = 0; q < 2; q++) {
                        const int nt = p * 2 + q;
                        mma_f16(c[0][nt], a[0], bb[p][2 * q], bb[p][2 * q + 1]);
                        mma_f16(c[1][nt], a[1], bb[p][2 * q], bb[p][2 * q + 1]);
                    }
            }
        }
    }

    #pragma unroll
    for (int mt = 0; mt < 2; mt++) {
        #pragma unroll
        for (int rr = 0; rr < 2; rr++) {
            const int m = warpM * 32 + mt * 16 + rr * 8 + g;
            const int py = ybase + (m >> 5);
            const int px = x0 + (m & 31);
            const size_t pos = ((size_t)b * 96 + py) * 96 + px;
            #pragma unroll
            for (int nt = 0; nt < NBT; nt++) {
                const int o = warpN * NWARP + nt * 8 + tg * 2;
                float v0 = c[mt][nt][rr * 2 + 0];
                float v1 = c[mt][nt][rr * 2 + 1];
                if constexpr (MODE == 0) {
                    const float2 pb = *(const float2*)&posbias[(size_t)(py * 96 + px) * 64 + o];
                    v0 += pb.x; v1 += pb.y;
                }
                const float2 sc = *(const float2*)&bnsc[o];
                const float2 shb = *(const float2*)&bnsh[o];
                v0 = fmaxf(fmaf(v0, sc.x, shb.x), 0.0f);
                v1 = fmaxf(fmaf(v1, sc.y, shb.y), 0.0f);
                *(__half2*)&out[pos * 64 + o] = __floats2half2_rn(v0, v1);
            }
        }
    }
}

// --------------- fused offset conv (64->18) + bilinear sampling ------------
__global__ void __launch_bounds__(256, 4)
offset_sample(const __half* __restrict__ in, const __half* __restrict__ wT,
              const float* __restrict__ chbias, __half* __restrict__ samp)
{
    constexpr int BN = 32;
    constexpr int KTOT = 576;
    constexpr int BSTG = BN * BPITCH;
    __shared__ float sOff[128 * 18];
    extern __shared__ __half smemh[];
    const unsigned hBase = smem_u32(smemh);
    const unsigned bBase = hBase + HBYTES;

    const int tid = threadIdx.x;
    const int wid = tid >> 5;
    const int lane = tid & 31;
    const int warpM = wid & 3;
    const int warpN = wid >> 2;
    const int g = lane >> 2;
    const int tg = lane & 3;

    const int x0 = blockIdx.x * 32;
    const int ybase = blockIdx.y * 4;
    const int b = blockIdx.z;

    const int lrow = lane & 7;
    const int lsel = lane >> 3;

    unsigned aAddrBase[2];
    #pragma unroll
    for (int mt = 0; mt < 2; mt++) {
        const int p = warpM * 32 + mt * 16 + lrow + ((lsel & 1) << 3);
        const int py = p >> 5, px = p & 31;
        aAddrBase[mt] = hBase
            + (unsigned)(((py + 1) * 34 + (px + 1)) * HPITCH
                         + ((lsel >> 1) << 3)) * 2u;
    }
    const int boff = (warpN * 16 + lrow + ((lsel >> 1) << 3)) * BPITCH
                   + ((lsel & 1) << 3);

    float c[2][2][4];
    #pragma unroll
    for (int mt = 0; mt < 2; mt++)
        #pragma unroll
        for (int nt = 0; nt < 2; nt++)
            #pragma unroll
            for (int r = 0; r < 4; r++) c[mt][nt][r] = 0.0f;

    auto prefetchB = [&](int ch, int buf) {
        if (tid < BN * 4) {
            const int o = tid >> 2;
            const int q = tid & 3;
            const int koff = (ch >> 1) * 64 + (ch & 1) * 32;
            const __half* ws = wT + (size_t)o * KTOT + koff + q * 8;
            unsigned dstB = bBase + (unsigned)(buf * BSTG + o * BPITCH) * 2u
                          + q * 16u;
            cp_async16(dstB, ws, true);
        }
    };

    if (tid < HROWS) {
        const int hr = tid / 34, hc = tid % 34;
        const int yy = ybase - 1 + hr, xx = x0 - 1 + hc;
        const bool ok = ((unsigned)yy < 96u) && ((unsigned)xx < 96u);
        const __half* src = ok
            ? in + (size_t)((b * 96 + yy) * 96 + xx) * 64
            : in;
        unsigned dst = hBase + (unsigned)(tid * HPITCH) * 2u;
        #pragma unroll
        for (int q = 0; q < 8; q++)
            cp_async16(dst + q * 16, src + q * 8, ok);
    }
    cp_commit();
    prefetchB(0, 0); cp_commit();
    prefetchB(1, 1); cp_commit();

    #pragma unroll
    for (int ch = 0; ch < 18; ch++) {
        cp_wait<1>();
        __syncthreads();
        if (ch + 2 < 18) prefetchB(ch + 2, (ch + 2) % 3);
        cp_commit();

        const int t = ch >> 1;
        const int dy = t / 3 - 1, dx = t % 3 - 1;
        const int aoffc = (dy * 34 + dx) * (HPITCH * 2) + (ch & 1) * 64;
        const unsigned bAddr = bBase + (unsigned)((ch % 3) * BSTG + boff) * 2u;

        #pragma unroll
        for (int ks = 0; ks < 2; ks++) {
            uint32_t a[2][4], bb[4];
            ldsm_x4(a[0], aAddrBase[0] + aoffc + ks * 32);
            ldsm_x4(a[1], aAddrBase[1] + aoffc + ks * 32);
            ldsm_x4(bb, bAddr + ks * 32);
            #pragma unroll
            for (int q = 0; q < 2; q++) {
                mma_f16(c[0][q], a[0], bb[2 * q], bb[2 * q + 1]);
                mma_f16(c[1][q], a[1], bb[2 * q], bb[2 * q + 1]);
            }
        }
    }

    // epilogue -> offsets into smem
    #pragma unroll
    for (int mt = 0; mt < 2; mt++) {
        #pragma unroll
        for (int rr = 0; rr < 2; rr++) {
            const int m = warpM * 32 + mt * 16 + rr * 8 + g;
            #pragma unroll
            for (int nt = 0; nt < 2; nt++) {
                const int o = warpN * 16 + nt * 8 + tg * 2;
                if (o < 18)
                    sOff[m * 18 + o] = c[mt][nt][rr * 2 + 0] + chbias[o];
                if (o + 1 < 18)
                    sOff[m * 18 + o + 1] = c[mt][nt][rr * 2 + 1] + chbias[o + 1];
            }
        }
    }
    __syncthreads();

    // sampling phase: 128 pos x 8 channel-quarters, 4 units per thread
    const uint4* img = (const uint4*)(in + (size_t)b * (96 * 96 * 64));
    #pragma unroll 1
    for (int u = 0; u < 4; u++) {
        const int unit = u * 256 + tid;
        const int lp = unit >> 3;
        const int cq = unit & 7;
        const int py = ybase + (lp >> 5);
        const int px = x0 + (lp & 31);
        const size_t gpos = ((size_t)b * 96 + py) * 96 + px;
        uint4* outp = (uint4*)(samp + gpos * 576);
        #pragma unroll
        for (int t = 0; t < 9; t++) {
            const float oy = sOff[lp * 18 + 2 * t];
            const float ox = sOff[lp * 18 + 2 * t + 1];
            const float pyf = (float)(py + t / 3 - 1) + oy;
            const float pxf = (float)(px + t % 3 - 1) + ox;
            const float y0f = floorf(pyf), x0f = floorf(pxf);
            const float fy = pyf - y0f, fx = pxf - x0f;
            const int iy = (int)y0f, ix = (int)x0f;
            const float w00 = (1.0f - fy) * (1.0f - fx);
            const float w01 = (1.0f - fy) * fx;
            const float w10 = fy * (1.0f - fx);
            const float w11 = fy * fx;
            float2 acc[4] = {{0.f,0.f},{0.f,0.f},{0.f,0.f},{0.f,0.f}};
            auto corner = [&](int yy, int xx, float w) {
                if ((unsigned)yy < 96u && (unsigned)xx < 96u) {
                    uint4 v = img[(yy * 96 + xx) * 8 + cq];
                    const __half2* hp = (const __half2*)&v;
                    #pragma unroll
                    for (int i = 0; i < 4; i++) {
                        float2 f = __half22float2(hp[i]);
                        acc[i].x = fmaf(w, f.x, acc[i].x);
                        acc[i].y = fmaf(w, f.y, acc[i].y);
                    }
                }
            };
            corner(iy,     ix,     w00);
            corner(iy,     ix + 1, w01);
            corner(iy + 1, ix,     w10);
            corner(iy + 1, ix + 1, w11);
            __half2 r[4];
            #pragma unroll
            for (int i = 0; i < 4; i++)
                r[i] = __floats2half2_rn(acc[i].x, acc[i].y);
            outp[t * 8 + cq] = *(uint4*)r;
        }
    }
}

// ---------------- fused r2 conv + BN4 + ReLU + 1x1 conv + sigmoid ----------
__global__ void __launch_bounds__(256, 4)
r2_final(const __half* __restrict__ in, const __half* __restrict__ wT,
         const float* __restrict__ bnsc, const float* __restrict__ bnsh,
         const float* __restrict__ ow, const float* __restrict__ ob,
         float* __restrict__ out)
{
    constexpr int BN = 64;
    constexpr int KTOT = 576;
    constexpr int BSTG = BN * BPITCH;
    __shared__ float sRed[2][128];
    extern __shared__ __half smemh[];
    const unsigned hBase = smem_u32(smemh);
    const unsigned bBase = hBase + HBYTES;

    const int tid = threadIdx.x;
    const int wid = tid >> 5;
    const int lane = tid & 31;
    const int warpM = wid & 3;
    const int warpN = wid >> 2;
    const int g = lane >> 2;
    const int tg = lane & 3;

    const int x0 = blockIdx.x * 32;
    const int ybase = blockIdx.y * 4;
    const int b = blockIdx.z;

    const int lrow = lane & 7;
    const int lsel = lane >> 3;

    unsigned aAddrBase[2];
    #pragma unroll
    for (int mt = 0; mt < 2; mt++) {
        const int p = warpM * 32 + mt * 16 + lrow + ((lsel & 1) << 3);
        const int py = p >> 5, px = p & 31;
        aAddrBase[mt] = hBase
            + (unsigned)(((py + 1) * 34 + (px + 1)) * HPITCH
                         + ((lsel >> 1) << 3)) * 2u;
    }
    const int boff = (warpN * 32 + lrow + ((lsel >> 1) << 3)) * BPITCH
                   + ((lsel & 1) << 3);

    float c[2][4][4];
    #pragma unroll
    for (int mt = 0; mt < 2; mt++)
        #pragma unroll
        for (int nt = 0; nt < 4; nt++)
            #pragma unroll
            for (int r = 0; r < 4; r++) c[mt][nt][r] = 0.0f;

    auto prefetchB = [&](int ch, int buf) {
        const int o = tid >> 2;
        const int q = tid & 3;
        const int koff = (ch >> 1) * 64 + (ch & 1) * 32;
        const __half* ws = wT + (size_t)o * KTOT + koff + q * 8;
        unsigned dstB = bBase + (unsigned)(buf * BSTG + o * BPITCH) * 2u
                      + q * 16u;
        cp_async16(dstB, ws, true);
    };

    if (tid < HROWS) {
        const int hr = tid / 34, hc = tid % 34;
        const int yy = ybase - 1 + hr, xx = x0 - 1 + hc;
        const bool ok = ((unsigned)yy < 96u) && ((unsigned)xx < 96u);
        const __half* src = ok
            ? in + (size_t)((b * 96 + yy) * 96 + xx) * 64
            : in;
        unsigned dst = hBase + (unsigned)(tid * HPITCH) * 2u;
        #pragma unroll
        for (int q = 0; q < 8; q++)
            cp_async16(dst + q * 16, src + q * 8, ok);
    }
    cp_commit();
    prefetchB(0, 0); cp_commit();
    prefetchB(1, 1); cp_commit();

    #pragma unroll
    for (int ch = 0; ch < 18; ch++) {
        cp_wait<1>();
        __syncthreads();
        if (ch + 2 < 18) prefetchB(ch + 2, (ch + 2) % 3);
        cp_commit();

        const int t = ch >> 1;
        const int dy = t / 3 - 1, dx = t % 3 - 1;
        const int aoffc = (dy * 34 + dx) * (HPITCH * 2) + (ch & 1) * 64;
        const unsigned bAddr = bBase + (unsigned)((ch % 3) * BSTG + boff) * 2u;

        #pragma unroll
        for (int ks = 0; ks < 2; ks++) {
            uint32_t a[2][4], bb[2][4];
            ldsm_x4(a[0], aAddrBase[0] + aoffc + ks * 32);
            ldsm_x4(a[1], aAddrBase[1] + aoffc + ks * 32);
            ldsm_x4(bb[0], bAddr + ks * 32);
            ldsm_x4(bb[1], bAddr + 16 * BPITCH * 2 + ks * 32);
            #pragma unroll
            for (int p = 0; p < 2; p++)
                #pragma unroll
                for (int q = 0; q < 2; q++) {
                    const int nt = p * 2 + q;
                    mma_f16(c[0][nt], a[0], bb[p][2 * q], bb[p][2 * q + 1]);
                    mma_f16(c[1][nt], a[1], bb[p][2 * q], bb[p][2 * q + 1]);
                }
        }
    }

    float part[4] = {0.f, 0.f, 0.f, 0.f};
    #pragma unroll
    for (int mt = 0; mt < 2; mt++) {
        #pragma unroll
        for (int rr = 0; rr < 2; rr++) {
            #pragma unroll
            for (int nt = 0; nt < 4; nt++) {
                const int o = warpN * 32 + nt * 8 + tg * 2;
                const float2 sc = *(const float2*)&bnsc[o];
                const float2 shb = *(const float2*)&bnsh[o];
                float v0 = fmaxf(fmaf(c[mt][nt][rr * 2 + 0], sc.x, shb.x), 0.0f);
                float v1 = fmaxf(fmaf(c[mt][nt][rr * 2 + 1], sc.y, shb.y), 0.0f);
                part[mt * 2 + rr] = fmaf(v0, ow[o],
                                    fmaf(v1, ow[o + 1], part[mt * 2 + rr]));
            }
        }
    }
    #pragma unroll
    for (int i = 0; i < 4; i++) {
        part[i] += __shfl_xor_sync(0xffffffffu, part[i], 1);
        part[i] += __shfl_xor_sync(0xffffffffu, part[i], 2);
    }
    if (tg == 0) {
        #pragma unroll
        for (int i = 0; i < 4; i++) {
            const int m = warpM * 32 + (i >> 1) * 16 + (i & 1) * 8 + g;
            sRed[warpN][m] = part[i];
        }
    }
    __syncthreads();
    if (tid < 128) {
        const int py = ybase + (tid >> 5);
        const int px = x0 + (tid & 31);
        const float s = sRed[0][tid] + sRed[1][tid] + ob[0];
        out[((size_t)b * 96 + py) * 96 + px] = 1.0f / (1.0f + expf(-s));
    }
}

// ------------------- streaming GEMM for deform einsum ----------------------
constexpr int STAGES = 3;
constexpr int PITCH = 40;
constexpr int ABUF_H = 128 * PITCH;

__global__ void __launch_bounds__(256, 4)
einsum_mma(const __half* __restrict__ in, const __half* __restrict__ wT,
           const float* __restrict__ bnsc, const float* __restrict__ bnsh,
           __half* __restrict__ out)
{
    constexpr int CIN = 576;
    constexpr int KCH = CIN / 32;
    constexpr int BBUF_H = 64 * PITCH;
    extern __shared__ __half smemh[];
    const unsigned aBase = smem_u32(smemh);
    const unsigned bBase = aBase + STAGES * ABUF_H * 2;

    const int tid = threadIdx.x;
    const int wid = tid >> 5;
    const int lane = tid & 31;
    const int warpM = wid & 3;
    const int warpN = wid >> 2;
    const int g = lane >> 2;
    const int tg = lane & 3;

    const int x0 = blockIdx.x * 32;
    const int ybase = blockIdx.y * 4;
    const int b = blockIdx.z;

    const int lrow = lane & 7;
    const int lsel = lane >> 3;
    const int aoff = (warpM * 32 + lrow + ((lsel & 1) << 3)) * PITCH
                   + ((lsel >> 1) << 3);
    const int boff = (warpN * 32 + lrow + ((lsel >> 1) << 3)) * PITCH
                   + ((lsel & 1) << 3);

    const int fp = tid >> 1;
    const int fhalf = (tid & 1) * 16;
    const int fpy = fp >> 5, fpx = fp & 31;

    float c[2][4][4];
    #pragma unroll
    for (int mt = 0; mt < 2; mt++)
        #pragma unroll
        for (int nt = 0; nt < 4; nt++)
            #pragma unroll
            for (int r = 0; r < 4; r++) c[mt][nt][r] = 0.0f;

    auto prefetch = [&](int ch) {
        const int s = ch % STAGES;
        const int c0 = ch * 32;
        const int yy = ybase + fpy;
        const int xx = x0 + fpx;
        const __half* src = in + (size_t)((b * 96 + yy) * 96 + xx) * CIN + c0 + fhalf;
        unsigned dstA = aBase + (unsigned)(s * ABUF_H + fp * PITCH + fhalf) * 2u;
        cp_async16(dstA, src, true);
        cp_async16(dstA + 16, src + 8, true);
        const int o = tid >> 2;
        const int q = tid & 3;
        const __half* ws = wT + (size_t)o * CIN + ch * 32 + q * 8;
        unsigned dstB = bBase + (unsigned)(s * BBUF_H + o * PITCH) * 2u + q * 16u;
        cp_async16(dstB, ws, true);
    };

    #pragma unroll
    for (int i = 0; i < STAGES - 1; i++) {
        prefetch(i);
        cp_commit();
    }

    for (int ch = 0; ch < KCH; ch++) {
        cp_wait<STAGES - 2>();
        __syncthreads();

        if (ch + STAGES - 1 < KCH) prefetch(ch + STAGES - 1);
        cp_commit();

        const int s = ch % STAGES;
        const unsigned aAddr = aBase + (unsigned)(s * ABUF_H + aoff) * 2u;
        const unsigned bAddr = bBase + (unsigned)(s * BBUF_H + boff) * 2u;

        #pragma unroll
        for (int ks = 0; ks < 2; ks++) {
            uint32_t a[2][4], bb[2][4];
            ldsm_x4(a[0], aAddr + ks * 32);
            ldsm_x4(a[1], aAddr + 16 * PITCH * 2 + ks * 32);
            ldsm_x4(bb[0], bAddr + ks * 32);
            ldsm_x4(bb[1], bAddr + 16 * PITCH * 2 + ks * 32);
            #pragma unroll
            for (int p = 0; p < 2; p++)
                #pragma unroll
                for (int q = 0; q < 2; q++) {
                    const int nt = p * 2 + q;
                    mma_f16(c[0][nt], a[0], bb[p][2 * q], bb[p][2 * q + 1]);
                    mma_f16(c[1][nt], a[1], bb[p][2 * q], bb[p][2 * q + 1]);
                }
        }
    }

    #pragma unroll
    for (int mt = 0; mt < 2; mt++) {
        #pragma unroll
        for (int rr = 0; rr < 2; rr++) {
            const int m = warpM * 32 + mt * 16 + rr * 8 + g;
            const int py = ybase + (m >> 5);
            const int px = x0 + (m & 31);
            const size_t pos = ((size_t)b * 96 + py) * 96 + px;
            #pragma unroll
            for (int nt = 0; nt < 4; nt++) {
                const int o = warpN * 32 + nt * 8 + tg * 2;
                float v0 = c[mt][nt][rr * 2 + 0];
                float v1 = c[mt][nt][rr * 2 + 1];
                const float2 sc = *(const float2*)&bnsc[o];
                const float2 shb = *(const float2*)&bnsh[o];
                v0 = fmaxf(fmaf(v0, sc.x, shb.x), 0.0f);
                v1 = fmaxf(fmaf(v1, sc.y, shb.y), 0.0f);
                *(__half2*)&out[pos * 64 + o] = __floats2half2_rn(v0, v1);
            }
        }
    }
}

// ------------------------------ launcher -----------------------------------
extern "C" void kernel_launch(void* const* d_in, const int* in_sizes, int n_in,
                              void* d_out, int out_size)
{
    const float* features = (const float*)d_in[0];
    const float* coord_w  = (const float*)d_in[1];
    const float* coord_b  = (const float*)d_in[2];
    const float* bn1g = (const float*)d_in[3];
    const float* bn1b = (const float*)d_in[4];
    const float* bn1m = (const float*)d_in[5];
    const float* bn1v = (const float*)d_in[6];
    const float* off_w = (const float*)d_in[7];
    const float* off_b = (const float*)d_in[8];
    const float* dc_w  = (const float*)d_in[9];
    const float* bn2g = (const float*)d_in[10];
    const float* bn2b = (const float*)d_in[11];
    const float* bn2m = (const float*)d_in[12];
    const float* bn2v = (const float*)d_in[13];
    const float* r1_w = (const float*)d_in[14];
    const float* bn3g = (const float*)d_in[15];
    const float* bn3b = (const float*)d_in[16];
    const float* bn3m = (const float*)d_in[17];
    const float* bn3v = (const float*)d_in[18];
    const float* r2_w = (const float*)d_in[19];
    const float* bn4g = (const float*)d_in[20];
    const float* bn4b = (const float*)d_in[21];
    const float* bn4m = (const float*)d_in[22];
    const float* bn4v = (const float*)d_in[23];
    const float* out_w = (const float*)d_in[24];
    const float* out_b = (const float*)d_in[25];

    __half *p_buf0, *p_buf1, *p_samp, *p_w1h, *p_woffh, *p_wdch,
           *p_wr1h, *p_wr2h;
    float *p_cb, *p_bnsc, *p_bnsh;
    cudaGetSymbolAddress((void**)&p_buf0, g_buf0h);
    cudaGetSymbolAddress((void**)&p_buf1, g_buf1h);
    cudaGetSymbolAddress((void**)&p_samp, g_samph);
    cudaGetSymbolAddress((void**)&p_w1h,  g_w1h);
    cudaGetSymbolAddress((void**)&p_woffh, g_woffh);
    cudaGetSymbolAddress((void**)&p_wdch, g_wdch);
    cudaGetSymbolAddress((void**)&p_wr1h, g_wr1h);
    cudaGetSymbolAddress((void**)&p_wr2h, g_wr2h);
    cudaGetSymbolAddress((void**)&p_cb,   g_cb);
    cudaGetSymbolAddress((void**)&p_bnsc, g_bnsc);
    cudaGetSymbolAddress((void**)&p_bnsh, g_bnsh);

    constexpr int HSM64 = HBYTES + 3 * 64 * BPITCH * 2;   // 44736
    constexpr int HSM32 = HBYTES + 3 * 32 * BPITCH * 2;   // 37056
    constexpr int ESM   = STAGES * (ABUF_H + 64 * PITCH) * 2;  // 46080

    cudaFuncSetAttribute(conv3x3_halo<true, 256, 64, 0>,
                         cudaFuncAttributeMaxDynamicSharedMemorySize, HSM64);
    cudaFuncSetAttribute(conv3x3_halo<false, 64, 64, 2>,
                         cudaFuncAttributeMaxDynamicSharedMemorySize, HSM64);
    cudaFuncSetAttribute(offset_sample,
                         cudaFuncAttributeMaxDynamicSharedMemorySize, HSM32);
    cudaFuncSetAttribute(r2_final,
                         cudaFuncAttributeMaxDynamicSharedMemorySize, HSM64);
    cudaFuncSetAttribute(einsum_mma,
                         cudaFuncAttributeMaxDynamicSharedMemorySize, ESM);

    // 1. prep: weight repack + coord bias map + folded BN (no f2h)
    const int prep_total = 64 * 2304 + 96 * 96 * 64
                         + 32 * 576 + 3 * 64 * 576 + 512;
    prep_kernel<<<(prep_total + 255) / 256, 256>>>(
        coord_w, coord_b, off_w, dc_w, r1_w, r2_w,
        bn1g, bn1b, bn1m, bn1v, bn2g, bn2b, bn2m, bn2v,
        bn3g, bn3b, bn3m, bn3v, bn4g, bn4b, bn4m, bn4v);

    dim3 grid(3, 24, 8);   // 32 x-cols, 4 rows -> 128 positions per block

    // 2. coord conv (fp32 in, 4 halo groups) + coord bias + BN1 + ReLU
    conv3x3_halo<true, 256, 64, 0><<<grid, 256, HSM64>>>(
        features, p_w1h, p_cb, p_bnsc + 0, p_bnsh + 0, p_buf0);

    // 3+4. offset conv (64->18) + bias + bilinear sampling -> g_samph
    offset_sample<<<grid, 256, HSM32>>>(p_buf0, p_woffh, off_b, p_samp);

    // 5. deform einsum (K=576, streaming) + BN2 + ReLU -> buf1
    einsum_mma<<<grid, 256, ESM>>>(
        p_samp, p_wdch, p_bnsc + 64, p_bnsh + 64, p_buf1);

    // 6. r1 conv + BN3 + ReLU -> buf0
    conv3x3_halo<false, 64, 64, 2><<<grid, 256, HSM64>>>(
        p_buf1, p_wr1h, nullptr, p_bnsc + 128, p_bnsh + 128, p_buf0);

    // 7+8. r2 conv + BN4 + ReLU + 1x1 conv + sigmoid -> d_out
    r2_final<<<grid, 256, HSM64>>>(
        p_buf0, p_wr2h, p_bnsc + 192, p_bnsh + 192, out_w, out_b,
        (float*)d_out);
}

// round 16
// speedup vs baseline: 1.0092x; 1.0021x over previous
#include <cuda_runtime.h>
#include <cuda_fp16.h>
#include <math.h>
#include <stdint.h>

// ---------------------------------------------------------------------------
// SpatialHead on sm_103a — fp16 mma + ldmatrix, halo-resident 3x3 convs
// (R12 structure). offset conv + sampling fused; r2 + 1x1 + sigmoid fused.
// Deform einsum uses 64-position blocks at 5 CTAs/SM for max DRAM MLP.
// ---------------------------------------------------------------------------

namespace sh {
constexpr int kB = 8, kH = 96, kW = 96;
constexpr int kPos = kB * kH * kW;          // 73728
constexpr float kEps = 1e-5f;
}

// ------------------------- scratch (__device__ globals) --------------------
__device__ __align__(16) __half g_feath[(size_t)sh::kPos * 256];
__device__ __align__(16) __half g_buf0h[sh::kPos * 64];
__device__ __align__(16) __half g_buf1h[sh::kPos * 64];
__device__ __align__(16) __half g_samph[(size_t)sh::kPos * 576];
__device__ __align__(16) __half g_w1h[64 * 2304];                 // [o][k]
__device__ __align__(16) __half g_woffh[32 * 576];
__device__ __align__(16) __half g_wdch[64 * 576];
__device__ __align__(16) __half g_wr1h[64 * 576];
__device__ __align__(16) __half g_wr2h[64 * 576];
__device__ __align__(16) float  g_cb[sh::kH * sh::kW * 64];
__device__ float g_bnsc[4 * 64];
__device__ float g_bnsh[4 * 64];

// ------------------------------ helpers ------------------------------------
__device__ __forceinline__ unsigned smem_u32(const void* p) {
    unsigned a;
    asm("{ .reg .u64 t; cvta.to.shared.u64 t, %1; cvt.u32.u64 %0, t; }"
        : "=r"(a) : "l"(p));
    return a;
}
__device__ __forceinline__ void cp_async16(unsigned dst, const void* src, bool ok) {
    int sz = ok ? 16 : 0;
    asm volatile("cp.async.cg.shared.global [%0], [%1], 16, %2;\n"
                 :: "r"(dst), "l"(src), "r"(sz));
}
__device__ __forceinline__ void cp_commit() {
    asm volatile("cp.async.commit_group;\n");
}
template <int N>
__device__ __forceinline__ void cp_wait() {
    asm volatile("cp.async.wait_group %0;\n" :: "n"(N));
}
__device__ __forceinline__ void ldsm_x4(uint32_t r[4], unsigned addr) {
    asm volatile("ldmatrix.sync.aligned.m8n8.x4.shared.b16 {%0,%1,%2,%3}, [%4];"
                 : "=r"(r[0]), "=r"(r[1]), "=r"(r[2]), "=r"(r[3]) : "r"(addr));
}
__device__ __forceinline__ void mma_f16(float c[4], const uint32_t a[4],
                                        uint32_t b0, uint32_t b1) {
    asm volatile(
        "mma.sync.aligned.m16n8k16.row.col.f32.f16.f16.f32 "
        "{%0,%1,%2,%3}, {%4,%5,%6,%7}, {%8,%9}, {%0,%1,%2,%3};\n"
        : "+f"(c[0]), "+f"(c[1]), "+f"(c[2]), "+f"(c[3])
        : "r"(a[0]), "r"(a[1]), "r"(a[2]), "r"(a[3]), "r"(b0), "r"(b1));
}
__device__ __forceinline__ uint32_t packh2(float a, float b) {
    __half2 p = __floats2half2_rn(a, b);
    return *(uint32_t*)&p;
}

// ------------------------------ prep kernel (incl. f2h) --------------------
__global__ void prep_kernel(
    const float* __restrict__ features,
    const float* __restrict__ coord_w, const float* __restrict__ coord_b,
    const float* __restrict__ off_w, const float* __restrict__ dc_w,
    const float* __restrict__ r1_w, const float* __restrict__ r2_w,
    const float* __restrict__ bn1g, const float* __restrict__ bn1b,
    const float* __restrict__ bn1m, const float* __restrict__ bn1v,
    const float* __restrict__ bn2g, const float* __restrict__ bn2b,
    const float* __restrict__ bn2m, const float* __restrict__ bn2v,
    const float* __restrict__ bn3g, const float* __restrict__ bn3b,
    const float* __restrict__ bn3m, const float* __restrict__ bn3v,
    const float* __restrict__ bn4g, const float* __restrict__ bn4b,
    const float* __restrict__ bn4m, const float* __restrict__ bn4v)
{
    int idx = blockIdx.x * blockDim.x + threadIdx.x;
    const int NF = sh::kPos * 32;
    const int N1 = 64 * 2304;
    const int N2 = sh::kH * sh::kW * 64;
    const int NOFF = 32 * 576;
    const int N3 = 64 * 576;

    if (idx < NF) {
        const float4* s = (const float4*)features + (size_t)idx * 2;
        float4 v0 = s[0], v1 = s[1];
        uint4 h;
        h.x = packh2(v0.x, v0.y); h.y = packh2(v0.z, v0.w);
        h.z = packh2(v1.x, v1.y); h.w = packh2(v1.z, v1.w);
        *(uint4*)&g_feath[(size_t)idx * 8] = h;
        return;
    }
    idx -= NF;
    if (idx < N1) {
        int o = idx / 2304, k = idx % 2304;
        int t = k >> 8, c = k & 255;
        g_w1h[idx] = __float2half(coord_w[(o * 258 + c) * 9 + t]);
        return;
    }
    idx -= N1;
    if (idx < N2) {
        int o = idx & 63, p = idx >> 6;
        int y = p / 96, x = p % 96;
        float acc = coord_b[o];
        #pragma unroll
        for (int t = 0; t < 9; t++) {
            int yy = y + t / 3 - 1, xx = x + t % 3 - 1;
            if ((unsigned)yy < 96u && (unsigned)xx < 96u) {
                float xv = fmaf((float)xx, 2.0f / 95.0f, -1.0f);
                float yv = fmaf((float)yy, 2.0f / 95.0f, -1.0f);
                acc = fmaf(coord_w[(o * 258 + 256) * 9 + t], xv, acc);
                acc = fmaf(coord_w[(o * 258 + 257) * 9 + t], yv, acc);
            }
        }
        g_cb[p * 64 + o] = acc;
        return;
    }
    idx -= N2;
    if (idx < NOFF) {
        int o = idx / 576, k = idx % 576;
        int t = k >> 6, c = k & 63;
        g_woffh[idx] = (o < 18) ? __float2half(off_w[(o * 64 + c) * 9 + t])
                                : __float2half(0.0f);
        return;
    }
    idx -= NOFF;
    if (idx < N3) {
        int o = idx / 576, k = idx % 576;
        int t = k >> 6, c = k & 63;
        g_wdch[idx] = __float2half(dc_w[(o * 64 + c) * 9 + t]);
        return;
    }
    idx -= N3;
    if (idx < N3) {
        int o = idx / 576, k = idx % 576;
        int t = k >> 6, c = k & 63;
        g_wr1h[idx] = __float2half(r1_w[(o * 64 + c) * 9 + t]);
        return;
    }
    idx -= N3;
    if (idx < N3) {
        int o = idx / 576, k = idx % 576;
        int t = k >> 6, c = k & 63;
        g_wr2h[idx] = __float2half(r2_w[(o * 64 + c) * 9 + t]);
        return;
    }
    idx -= N3;
    if (idx < 512) {
        int which = idx >> 7, r = idx & 127, o = r & 63;
        const float* gs; const float* bs; const float* ms; const float* vs;
        if (which == 0)      { gs = bn1g; bs = bn1b; ms = bn1m; vs = bn1v; }
        else if (which == 1) { gs = bn2g; bs = bn2b; ms = bn2m; vs = bn2v; }
        else if (which == 2) { gs = bn3g; bs = bn3b; ms = bn3m; vs = bn3v; }
        else                 { gs = bn4g; bs = bn4b; ms = bn4m; vs = bn4v; }
        float sc = gs[o] * rsqrtf(vs[o] + sh::kEps);
        if (r < 64) g_bnsc[which * 64 + o] = sc;
        else        g_bnsh[which * 64 + o] = bs[o] - ms[o] * sc;
    }
}

// ------------------- 3x3 conv with smem-resident halo tile -----------------
constexpr int HPITCH = 72;                  // halves per halo position
constexpr int HROWS = 6 * 34;               // 204
constexpr int HBYTES = HROWS * HPITCH * 2;  // 29376
constexpr int BPITCH = 40;                  // halves per weight row

template <int CIN, int BN, int MODE>
__global__ void __launch_bounds__(256, 4)
conv3x3_halo(const __half* __restrict__ in, const __half* __restrict__ wT,
             const float* __restrict__ posbias,
             const float* __restrict__ bnsc, const float* __restrict__ bnsh,
             __half* __restrict__ out)
{
    constexpr int NGRP = CIN / 64;
    constexpr int KTOT = 9 * CIN;
    constexpr int BSTG = BN * BPITCH;
    constexpr int NWARP = BN / 2;
    constexpr int NBT = NWARP / 8;
    extern __shared__ __half smemh[];
    const unsigned hBase = smem_u32(smemh);
    const unsigned bBase = hBase + HBYTES;

    const int tid = threadIdx.x;
    const int wid = tid >> 5;
    const int lane = tid & 31;
    const int warpM = wid & 3;
    const int warpN = wid >> 2;
    const int g = lane >> 2;
    const int tg = lane & 3;

    const int x0 = blockIdx.x * 32;
    const int ybase = blockIdx.y * 4;
    const int b = blockIdx.z;

    const int lrow = lane & 7;
    const int lsel = lane >> 3;

    unsigned aAddrBase[2];
    #pragma unroll
    for (int mt = 0; mt < 2; mt++) {
        const int p = warpM * 32 + mt * 16 + lrow + ((lsel & 1) << 3);
        const int py = p >> 5, px = p & 31;
        aAddrBase[mt] = hBase
            + (unsigned)(((py + 1) * 34 + (px + 1)) * HPITCH
                         + ((lsel >> 1) << 3)) * 2u;
    }
    const int boff = (warpN * NWARP + lrow + ((lsel >> 1) << 3)) * BPITCH
                   + ((lsel & 1) << 3);

    float c[2][NBT][4];
    #pragma unroll
    for (int mt = 0; mt < 2; mt++)
        #pragma unroll
        for (int nt = 0; nt < NBT; nt++)
            #pragma unroll
            for (int r = 0; r < 4; r++) c[mt][nt][r] = 0.0f;

    auto prefetchB = [&](int grp, int ch, int buf) {
        if (tid < BN * 4) {
            const int o = tid >> 2;
            const int q = tid & 3;
            const int koff = (ch >> 1) * CIN + grp * 64 + (ch & 1) * 32;
            const __half* ws = wT + (size_t)o * KTOT + koff + q * 8;
            unsigned dstB = bBase + (unsigned)(buf * BSTG + o * BPITCH) * 2u
                          + q * 16u;
            cp_async16(dstB, ws, true);
        }
    };

    for (int grp = 0; grp < NGRP; grp++) {
        __syncthreads();
        if (tid < HROWS) {
            const int hr = tid / 34, hc = tid % 34;
            const int yy = ybase - 1 + hr, xx = x0 - 1 + hc;
            const bool ok = ((unsigned)yy < 96u) && ((unsigned)xx < 96u);
            const __half* src = ok
                ? in + (size_t)((b * 96 + yy) * 96 + xx) * CIN + grp * 64
                : in;
            unsigned dst = hBase + (unsigned)(tid * HPITCH) * 2u;
            #pragma unroll
            for (int q = 0; q < 8; q++)
                cp_async16(dst + q * 16, src + q * 8, ok);
        }
        cp_commit();
        prefetchB(grp, 0, 0); cp_commit();
        prefetchB(grp, 1, 1); cp_commit();

        #pragma unroll
        for (int ch = 0; ch < 18; ch++) {
            cp_wait<1>();
            __syncthreads();
            if (ch + 2 < 18) prefetchB(grp, ch + 2, (ch + 2) % 3);
            cp_commit();

            const int t = ch >> 1;
            const int dy = t / 3 - 1, dx = t % 3 - 1;
            const int aoffc = (dy * 34 + dx) * (HPITCH * 2) + (ch & 1) * 64;
            const unsigned bAddr = bBase
                + (unsigned)((ch % 3) * BSTG + boff) * 2u;

            #pragma unroll
            for (int ks = 0; ks < 2; ks++) {
                uint32_t a[2][4], bb[NBT / 2][4];
                ldsm_x4(a[0], aAddrBase[0] + aoffc + ks * 32);
                ldsm_x4(a[1], aAddrBase[1] + aoffc + ks * 32);
                #pragma unroll
                for (int p = 0; p < NBT / 2; p++)
                    ldsm_x4(bb[p], bAddr + p * 16 * BPITCH * 2 + ks * 32);
                #pragma unroll
                for (int p = 0; p < NBT / 2; p++)
                    #pragma unroll
                    for (int q = 0; q < 2; q++) {
                        const int nt = p * 2 + q;
                        mma_f16(c[0][nt], a[0], bb[p][2 * q], bb[p][2 * q + 1]);
                        mma_f16(c[1][nt], a[1], bb[p][2 * q], bb[p][2 * q + 1]);
                    }
            }
        }
    }

    #pragma unroll
    for (int mt = 0; mt < 2; mt++) {
        #pragma unroll
        for (int rr = 0; rr < 2; rr++) {
            const int m = warpM * 32 + mt * 16 + rr * 8 + g;
            const int py = ybase + (m >> 5);
            const int px = x0 + (m & 31);
            const size_t pos = ((size_t)b * 96 + py) * 96 + px;
            #pragma unroll
            for (int nt = 0; nt < NBT; nt++) {
                const int o = warpN * NWARP + nt * 8 + tg * 2;
                float v0 = c[mt][nt][rr * 2 + 0];
                float v1 = c[mt][nt][rr * 2 + 1];
                if constexpr (MODE == 0) {
                    const float2 pb = *(const float2*)&posbias[(size_t)(py * 96 + px) * 64 + o];
                    v0 += pb.x; v1 += pb.y;
                }
                const float2 sc = *(const float2*)&bnsc[o];
                const float2 shb = *(const float2*)&bnsh[o];
                v0 = fmaxf(fmaf(v0, sc.x, shb.x), 0.0f);
                v1 = fmaxf(fmaf(v1, sc.y, shb.y), 0.0f);
                *(__half2*)&out[pos * 64 + o] = __floats2half2_rn(v0, v1);
            }
        }
    }
}

// --------------- fused offset conv (64->18) + bilinear sampling ------------
__global__ void __launch_bounds__(256, 4)
offset_sample(const __half* __restrict__ in, const __half* __restrict__ wT,
              const float* __restrict__ chbias, __half* __restrict__ samp)
{
    constexpr int BN = 32;
    constexpr int KTOT = 576;
    constexpr int BSTG = BN * BPITCH;
    __shared__ float sOff[128 * 18];
    extern __shared__ __half smemh[];
    const unsigned hBase = smem_u32(smemh);
    const unsigned bBase = hBase + HBYTES;

    const int tid = threadIdx.x;
    const int wid = tid >> 5;
    const int lane = tid & 31;
    const int warpM = wid & 3;
    const int warpN = wid >> 2;
    const int g = lane >> 2;
    const int tg = lane & 3;

    const int x0 = blockIdx.x * 32;
    const int ybase = blockIdx.y * 4;
    const int b = blockIdx.z;

    const int lrow = lane & 7;
    const int lsel = lane >> 3;

    unsigned aAddrBase[2];
    #pragma unroll
    for (int mt = 0; mt < 2; mt++) {
        const int p = warpM * 32 + mt * 16 + lrow + ((lsel & 1) << 3);
        const int py = p >> 5, px = p & 31;
        aAddrBase[mt] = hBase
            + (unsigned)(((py + 1) * 34 + (px + 1)) * HPITCH
                         + ((lsel >> 1) << 3)) * 2u;
    }
    const int boff = (warpN * 16 + lrow + ((lsel >> 1) << 3)) * BPITCH
                   + ((lsel & 1) << 3);

    float c[2][2][4];
    #pragma unroll
    for (int mt = 0; mt < 2; mt++)
        #pragma unroll
        for (int nt = 0; nt < 2; nt++)
            #pragma unroll
            for (int r = 0; r < 4; r++) c[mt][nt][r] = 0.0f;

    auto prefetchB = [&](int ch, int buf) {
        if (tid < BN * 4) {
            const int o = tid >> 2;
            const int q = tid & 3;
            const int koff = (ch >> 1) * 64 + (ch & 1) * 32;
            const __half* ws = wT + (size_t)o * KTOT + koff + q * 8;
            unsigned dstB = bBase + (unsigned)(buf * BSTG + o * BPITCH) * 2u
                          + q * 16u;
            cp_async16(dstB, ws, true);
        }
    };

    if (tid < HROWS) {
        const int hr = tid / 34, hc = tid % 34;
        const int yy = ybase - 1 + hr, xx = x0 - 1 + hc;
        const bool ok = ((unsigned)yy < 96u) && ((unsigned)xx < 96u);
        const __half* src = ok
            ? in + (size_t)((b * 96 + yy) * 96 + xx) * 64
            : in;
        unsigned dst = hBase + (unsigned)(tid * HPITCH) * 2u;
        #pragma unroll
        for (int q = 0; q < 8; q++)
            cp_async16(dst + q * 16, src + q * 8, ok);
    }
    cp_commit();
    prefetchB(0, 0); cp_commit();
    prefetchB(1, 1); cp_commit();

    #pragma unroll
    for (int ch = 0; ch < 18; ch++) {
        cp_wait<1>();
        __syncthreads();
        if (ch + 2 < 18) prefetchB(ch + 2, (ch + 2) % 3);
        cp_commit();

        const int t = ch >> 1;
        const int dy = t / 3 - 1, dx = t % 3 - 1;
        const int aoffc = (dy * 34 + dx) * (HPITCH * 2) + (ch & 1) * 64;
        const unsigned bAddr = bBase + (unsigned)((ch % 3) * BSTG + boff) * 2u;

        #pragma unroll
        for (int ks = 0; ks < 2; ks++) {
            uint32_t a[2][4], bb[4];
            ldsm_x4(a[0], aAddrBase[0] + aoffc + ks * 32);
            ldsm_x4(a[1], aAddrBase[1] + aoffc + ks * 32);
            ldsm_x4(bb, bAddr + ks * 32);
            #pragma unroll
            for (int q = 0; q < 2; q++) {
                mma_f16(c[0][q], a[0], bb[2 * q], bb[2 * q + 1]);
                mma_f16(c[1][q], a[1], bb[2 * q], bb[2 * q + 1]);
            }
        }
    }

    // epilogue -> offsets into smem
    #pragma unroll
    for (int mt = 0; mt < 2; mt++) {
        #pragma unroll
        for (int rr = 0; rr < 2; rr++) {
            const int m = warpM * 32 + mt * 16 + rr * 8 + g;
            #pragma unroll
            for (int nt = 0; nt < 2; nt++) {
                const int o = warpN * 16 + nt * 8 + tg * 2;
                if (o < 18)
                    sOff[m * 18 + o] = c[mt][nt][rr * 2 + 0] + chbias[o];
                if (o + 1 < 18)
                    sOff[m * 18 + o + 1] = c[mt][nt][rr * 2 + 1] + chbias[o + 1];
            }
        }
    }
    __syncthreads();

    // sampling phase: 128 pos x 8 channel-quarters, 4 units per thread
    const uint4* img = (const uint4*)(in + (size_t)b * (96 * 96 * 64));
    #pragma unroll 1
    for (int u = 0; u < 4; u++) {
        const int unit = u * 256 + tid;
        const int lp = unit >> 3;
        const int cq = unit & 7;
        const int py = ybase + (lp >> 5);
        const int px = x0 + (lp & 31);
        const size_t gpos = ((size_t)b * 96 + py) * 96 + px;
        uint4* outp = (uint4*)(samp + gpos * 576);
        #pragma unroll
        for (int t = 0; t < 9; t++) {
            const float oy = sOff[lp * 18 + 2 * t];
            const float ox = sOff[lp * 18 + 2 * t + 1];
            const float pyf = (float)(py + t / 3 - 1) + oy;
            const float pxf = (float)(px + t % 3 - 1) + ox;
            const float y0f = floorf(pyf), x0f = floorf(pxf);
            const float fy = pyf - y0f, fx = pxf - x0f;
            const int iy = (int)y0f, ix = (int)x0f;
            const float w00 = (1.0f - fy) * (1.0f - fx);
            const float w01 = (1.0f - fy) * fx;
            const float w10 = fy * (1.0f - fx);
            const float w11 = fy * fx;
            float2 acc[4] = {{0.f,0.f},{0.f,0.f},{0.f,0.f},{0.f,0.f}};
            auto corner = [&](int yy, int xx, float w) {
                if ((unsigned)yy < 96u && (unsigned)xx < 96u) {
                    uint4 v = img[(yy * 96 + xx) * 8 + cq];
                    const __half2* hp = (const __half2*)&v;
                    #pragma unroll
                    for (int i = 0; i < 4; i++) {
                        float2 f = __half22float2(hp[i]);
                        acc[i].x = fmaf(w, f.x, acc[i].x);
                        acc[i].y = fmaf(w, f.y, acc[i].y);
                    }
                }
            };
            corner(iy,     ix,     w00);
            corner(iy,     ix + 1, w01);
            corner(iy + 1, ix,     w10);
            corner(iy + 1, ix + 1, w11);
            __half2 r[4];
            #pragma unroll
            for (int i = 0; i < 4; i++)
                r[i] = __floats2half2_rn(acc[i].x, acc[i].y);
            outp[t * 8 + cq] = *(uint4*)r;
        }
    }
}

// ---------------- fused r2 conv + BN4 + ReLU + 1x1 conv + sigmoid ----------
__global__ void __launch_bounds__(256, 4)
r2_final(const __half* __restrict__ in, const __half* __restrict__ wT,
         const float* __restrict__ bnsc, const float* __restrict__ bnsh,
         const float* __restrict__ ow, const float* __restrict__ ob,
         float* __restrict__ out)
{
    constexpr int BN = 64;
    constexpr int KTOT = 576;
    constexpr int BSTG = BN * BPITCH;
    __shared__ float sRed[2][128];
    extern __shared__ __half smemh[];
    const unsigned hBase = smem_u32(smemh);
    const unsigned bBase = hBase + HBYTES;

    const int tid = threadIdx.x;
    const int wid = tid >> 5;
    const int lane = tid & 31;
    const int warpM = wid & 3;
    const int warpN = wid >> 2;
    const int g = lane >> 2;
    const int tg = lane & 3;

    const int x0 = blockIdx.x * 32;
    const int ybase = blockIdx.y * 4;
    const int b = blockIdx.z;

    const int lrow = lane & 7;
    const int lsel = lane >> 3;

    unsigned aAddrBase[2];
    #pragma unroll
    for (int mt = 0; mt < 2; mt++) {
        const int p = warpM * 32 + mt * 16 + lrow + ((lsel & 1) << 3);
        const int py = p >> 5, px = p & 31;
        aAddrBase[mt] = hBase
            + (unsigned)(((py + 1) * 34 + (px + 1)) * HPITCH
                         + ((lsel >> 1) << 3)) * 2u;
    }
    const int boff = (warpN * 32 + lrow + ((lsel >> 1) << 3)) * BPITCH
                   + ((lsel & 1) << 3);

    float c[2][4][4];
    #pragma unroll
    for (int mt = 0; mt < 2; mt++)
        #pragma unroll
        for (int nt = 0; nt < 4; nt++)
            #pragma unroll
            for (int r = 0; r < 4; r++) c[mt][nt][r] = 0.0f;

    auto prefetchB = [&](int ch, int buf) {
        const int o = tid >> 2;
        const int q = tid & 3;
        const int koff = (ch >> 1) * 64 + (ch & 1) * 32;
        const __half* ws = wT + (size_t)o * KTOT + koff + q * 8;
        unsigned dstB = bBase + (unsigned)(buf * BSTG + o * BPITCH) * 2u
                      + q * 16u;
        cp_async16(dstB, ws, true);
    };

    if (tid < HROWS) {
        const int hr = tid / 34, hc = tid % 34;
        const int yy = ybase - 1 + hr, xx = x0 - 1 + hc;
        const bool ok = ((unsigned)yy < 96u) && ((unsigned)xx < 96u);
        const __half* src = ok
            ? in + (size_t)((b * 96 + yy) * 96 + xx) * 64
            : in;
        unsigned dst = hBase + (unsigned)(tid * HPITCH) * 2u;
        #pragma unroll
        for (int q = 0; q < 8; q++)
            cp_async16(dst + q * 16, src + q * 8, ok);
    }
    cp_commit();
    prefetchB(0, 0); cp_commit();
    prefetchB(1, 1); cp_commit();

    #pragma unroll
    for (int ch = 0; ch < 18; ch++) {
        cp_wait<1>();
        __syncthreads();
        if (ch + 2 < 18) prefetchB(ch + 2, (ch + 2) % 3);
        cp_commit();

        const int t = ch >> 1;
        const int dy = t / 3 - 1, dx = t % 3 - 1;
        const int aoffc = (dy * 34 + dx) * (HPITCH * 2) + (ch & 1) * 64;
        const unsigned bAddr = bBase + (unsigned)((ch % 3) * BSTG + boff) * 2u;

        #pragma unroll
        for (int ks = 0; ks < 2; ks++) {
            uint32_t a[2][4], bb[2][4];
            ldsm_x4(a[0], aAddrBase[0] + aoffc + ks * 32);
            ldsm_x4(a[1], aAddrBase[1] + aoffc + ks * 32);
            ldsm_x4(bb[0], bAddr + ks * 32);
            ldsm_x4(bb[1], bAddr + 16 * BPITCH * 2 + ks * 32);
            #pragma unroll
            for (int p = 0; p < 2; p++)
                #pragma unroll
                for (int q = 0; q < 2; q++) {
                    const int nt = p * 2 + q;
                    mma_f16(c[0][nt], a[0], bb[p][2 * q], bb[p][2 * q + 1]);
                    mma_f16(c[1][nt], a[1], bb[p][2 * q], bb[p][2 * q + 1]);
                }
        }
    }

    float part[4] = {0.f, 0.f, 0.f, 0.f};
    #pragma unroll
    for (int mt = 0; mt < 2; mt++) {
        #pragma unroll
        for (int rr = 0; rr < 2; rr++) {
            #pragma unroll
            for (int nt = 0; nt < 4; nt++) {
                const int o = warpN * 32 + nt * 8 + tg * 2;
                const float2 sc = *(const float2*)&bnsc[o];
                const float2 shb = *(const float2*)&bnsh[o];
                float v0 = fmaxf(fmaf(c[mt][nt][rr * 2 + 0], sc.x, shb.x), 0.0f);
                float v1 = fmaxf(fmaf(c[mt][nt][rr * 2 + 1], sc.y, shb.y), 0.0f);
                part[mt * 2 + rr] = fmaf(v0, ow[o],
                                    fmaf(v1, ow[o + 1], part[mt * 2 + rr]));
            }
        }
    }
    #pragma unroll
    for (int i = 0; i < 4; i++) {
        part[i] += __shfl_xor_sync(0xffffffffu, part[i], 1);
        part[i] += __shfl_xor_sync(0xffffffffu, part[i], 2);
    }
    if (tg == 0) {
        #pragma unroll
        for (int i = 0; i < 4; i++) {
            const int m = warpM * 32 + (i >> 1) * 16 + (i & 1) * 8 + g;
            sRed[warpN][m] = part[i];
        }
    }
    __syncthreads();
    if (tid < 128) {
        const int py = ybase + (tid >> 5);
        const int px = x0 + (tid & 31);
        const float s = sRed[0][tid] + sRed[1][tid] + ob[0];
        out[((size_t)b * 96 + py) * 96 + px] = 1.0f / (1.0f + expf(-s));
    }
}

// ------------- streaming GEMM for deform einsum (64-pos blocks) ------------
// Block: 64 positions (2 rows x 32 cols) x 64 cout, 256 threads, 8 warps
// (2 warpM x m32, 4 warpN x n16). 3-stage cp.async; 5 CTAs/SM for DRAM MLP.
constexpr int STAGES = 3;
constexpr int PITCH = 40;
constexpr int EA_H = 64 * PITCH;            // A stage halves (2560)
constexpr int EB_H = 64 * PITCH;            // B stage halves (2560)
constexpr int ESM = STAGES * (EA_H + EB_H) * 2;  // 30720 bytes

__global__ void __launch_bounds__(256, 5)
einsum_mma(const __half* __restrict__ in, const __half* __restrict__ wT,
           const float* __restrict__ bnsc, const float* __restrict__ bnsh,
           __half* __restrict__ out)
{
    constexpr int CIN = 576;
    constexpr int KCH = CIN / 32;
    extern __shared__ __half smemh[];
    const unsigned aBase = smem_u32(smemh);
    const unsigned bBase = aBase + STAGES * EA_H * 2;

    const int tid = threadIdx.x;
    const int wid = tid >> 5;
    const int lane = tid & 31;
    const int warpM = wid & 1;           // m32 each
    const int warpN = wid >> 1;          // n16 each (0..3)
    const int g = lane >> 2;
    const int tg = lane & 3;

    const int x0 = blockIdx.x * 32;
    const int ybase = blockIdx.y * 2;
    const int b = blockIdx.z;

    const int lrow = lane & 7;
    const int lsel = lane >> 3;
    const int aoff = (warpM * 32 + lrow + ((lsel & 1) << 3)) * PITCH
                   + ((lsel >> 1) << 3);
    const int boff = (warpN * 16 + lrow + ((lsel >> 1) << 3)) * PITCH
                   + ((lsel & 1) << 3);

    // fill mapping: thread covers quarter of a position row (16B)
    const int fp = tid >> 2;             // position 0..63
    const int fq = tid & 3;              // 16B quarter
    const int fpy = fp >> 5, fpx = fp & 31;

    float c[2][2][4];
    #pragma unroll
    for (int mt = 0; mt < 2; mt++)
        #pragma unroll
        for (int nt = 0; nt < 2; nt++)
            #pragma unroll
            for (int r = 0; r < 4; r++) c[mt][nt][r] = 0.0f;

    auto prefetch = [&](int ch) {
        const int s = ch % STAGES;
        const int c0 = ch * 32;
        const int yy = ybase + fpy;
        const int xx = x0 + fpx;
        const __half* srcA = in + (size_t)((b * 96 + yy) * 96 + xx) * CIN
                           + c0 + fq * 8;
        unsigned dstA = aBase + (unsigned)(s * EA_H + fp * PITCH) * 2u + fq * 16u;
        cp_async16(dstA, srcA, true);
        const __half* srcB = wT + (size_t)fp * CIN + c0 + fq * 8;
        unsigned dstB = bBase + (unsigned)(s * EB_H + fp * PITCH) * 2u + fq * 16u;
        cp_async16(dstB, srcB, true);
    };

    #pragma unroll
    for (int i = 0; i < STAGES - 1; i++) {
        prefetch(i);
        cp_commit();
    }

    for (int ch = 0; ch < KCH; ch++) {
        cp_wait<STAGES - 2>();
        __syncthreads();

        if (ch + STAGES - 1 < KCH) prefetch(ch + STAGES - 1);
        cp_commit();

        const int s = ch % STAGES;
        const unsigned aAddr = aBase + (unsigned)(s * EA_H + aoff) * 2u;
        const unsigned bAddr = bBase + (unsigned)(s * EB_H + boff) * 2u;

        #pragma unroll
        for (int ks = 0; ks < 2; ks++) {
            uint32_t a[2][4], bb[4];
            ldsm_x4(a[0], aAddr + ks * 32);
            ldsm_x4(a[1], aAddr + 16 * PITCH * 2 + ks * 32);
            ldsm_x4(bb, bAddr + ks * 32);
            #pragma unroll
            for (int q = 0; q < 2; q++) {
                mma_f16(c[0][q], a[0], bb[2 * q], bb[2 * q + 1]);
                mma_f16(c[1][q], a[1], bb[2 * q], bb[2 * q + 1]);
            }
        }
    }

    #pragma unroll
    for (int mt = 0; mt < 2; mt++) {
        #pragma unroll
        for (int rr = 0; rr < 2; rr++) {
            const int m = warpM * 32 + mt * 16 + rr * 8 + g;
            const int py = ybase + (m >> 5);
            const int px = x0 + (m & 31);
            const size_t pos = ((size_t)b * 96 + py) * 96 + px;
            #pragma unroll
            for (int nt = 0; nt < 2; nt++) {
                const int o = warpN * 16 + nt * 8 + tg * 2;
                float v0 = c[mt][nt][rr * 2 + 0];
                float v1 = c[mt][nt][rr * 2 + 1];
                const float2 sc = *(const float2*)&bnsc[o];
                const float2 shb = *(const float2*)&bnsh[o];
                v0 = fmaxf(fmaf(v0, sc.x, shb.x), 0.0f);
                v1 = fmaxf(fmaf(v1, sc.y, shb.y), 0.0f);
                *(__half2*)&out[pos * 64 + o] = __floats2half2_rn(v0, v1);
            }
        }
    }
}

// ------------------------------ launcher -----------------------------------
extern "C" void kernel_launch(void* const* d_in, const int* in_sizes, int n_in,
                              void* d_out, int out_size)
{
    const float* features = (const float*)d_in[0];
    const float* coord_w  = (const float*)d_in[1];
    const float* coord_b  = (const float*)d_in[2];
    const float* bn1g = (const float*)d_in[3];
    const float* bn1b = (const float*)d_in[4];
    const float* bn1m = (const float*)d_in[5];
    const float* bn1v = (const float*)d_in[6];
    const float* off_w = (const float*)d_in[7];
    const float* off_b = (const float*)d_in[8];
    const float* dc_w  = (const float*)d_in[9];
    const float* bn2g = (const float*)d_in[10];
    const float* bn2b = (const float*)d_in[11];
    const float* bn2m = (const float*)d_in[12];
    const float* bn2v = (const float*)d_in[13];
    const float* r1_w = (const float*)d_in[14];
    const float* bn3g = (const float*)d_in[15];
    const float* bn3b = (const float*)d_in[16];
    const float* bn3m = (const float*)d_in[17];
    const float* bn3v = (const float*)d_in[18];
    const float* r2_w = (const float*)d_in[19];
    const float* bn4g = (const float*)d_in[20];
    const float* bn4b = (const float*)d_in[21];
    const float* bn4m = (const float*)d_in[22];
    const float* bn4v = (const float*)d_in[23];
    const float* out_w = (const float*)d_in[24];
    const float* out_b = (const float*)d_in[25];

    __half *p_feath, *p_buf0, *p_buf1, *p_samp, *p_w1h, *p_woffh, *p_wdch,
           *p_wr1h, *p_wr2h;
    float *p_cb, *p_bnsc, *p_bnsh;
    cudaGetSymbolAddress((void**)&p_feath, g_feath);
    cudaGetSymbolAddress((void**)&p_buf0, g_buf0h);
    cudaGetSymbolAddress((void**)&p_buf1, g_buf1h);
    cudaGetSymbolAddress((void**)&p_samp, g_samph);
    cudaGetSymbolAddress((void**)&p_w1h,  g_w1h);
    cudaGetSymbolAddress((void**)&p_woffh, g_woffh);
    cudaGetSymbolAddress((void**)&p_wdch, g_wdch);
    cudaGetSymbolAddress((void**)&p_wr1h, g_wr1h);
    cudaGetSymbolAddress((void**)&p_wr2h, g_wr2h);
    cudaGetSymbolAddress((void**)&p_cb,   g_cb);
    cudaGetSymbolAddress((void**)&p_bnsc, g_bnsc);
    cudaGetSymbolAddress((void**)&p_bnsh, g_bnsh);

    constexpr int HSM64 = HBYTES + 3 * 64 * BPITCH * 2;   // 44736
    constexpr int HSM32 = HBYTES + 3 * 32 * BPITCH * 2;   // 37056

    cudaFuncSetAttribute(conv3x3_halo<256, 64, 0>,
                         cudaFuncAttributeMaxDynamicSharedMemorySize, HSM64);
    cudaFuncSetAttribute(conv3x3_halo<64, 64, 2>,
                         cudaFuncAttributeMaxDynamicSharedMemorySize, HSM64);
    cudaFuncSetAttribute(offset_sample,
                         cudaFuncAttributeMaxDynamicSharedMemorySize, HSM32);
    cudaFuncSetAttribute(r2_final,
                         cudaFuncAttributeMaxDynamicSharedMemorySize, HSM64);
    cudaFuncSetAttribute(einsum_mma,
                         cudaFuncAttributeMaxDynamicSharedMemorySize, ESM);

    // 1. prep: f2h + weight repack + coord bias map + folded BN
    const int prep_total = sh::kPos * 32 + 64 * 2304 + 96 * 96 * 64
                         + 32 * 576 + 3 * 64 * 576 + 512;
    prep_kernel<<<(prep_total + 255) / 256, 256>>>(
        features, coord_w, coord_b, off_w, dc_w, r1_w, r2_w,
        bn1g, bn1b, bn1m, bn1v, bn2g, bn2b, bn2m, bn2v,
        bn3g, bn3b, bn3m, bn3v, bn4g, bn4b, bn4m, bn4v);

    dim3 grid(3, 24, 8);   // 32 x-cols, 4 rows -> 128 positions per block

    // 2. coord conv (256->64, 4 halo groups) + coord bias + BN1 + ReLU
    conv3x3_halo<256, 64, 0><<<grid, 256, HSM64>>>(
        p_feath, p_w1h, p_cb, p_bnsc + 0, p_bnsh + 0, p_buf0);

    // 3+4. offset conv (64->18) + bias + bilinear sampling -> g_samph
    offset_sample<<<grid, 256, HSM32>>>(p_buf0, p_woffh, off_b, p_samp);

    // 5. deform einsum (K=576, 64-pos blocks) + BN2 + ReLU -> buf1
    dim3 egrid(3, 48, 8);
    einsum_mma<<<egrid, 256, ESM>>>(
        p_samp, p_wdch, p_bnsc + 64, p_bnsh + 64, p_buf1);

    // 6. r1 conv + BN3 + ReLU -> buf0
    conv3x3_halo<64, 64, 2><<<grid, 256, HSM64>>>(
        p_buf1, p_wr1h, nullptr, p_bnsc + 128, p_bnsh + 128, p_buf0);

    // 7+8. r2 conv + BN4 + ReLU + 1x1 conv + sigmoid -> d_out
    r2_final<<<grid, 256, HSM64>>>(
        p_buf0, p_wr2h, p_bnsc + 192, p_bnsh + 192, out_w, out_b,
        (float*)d_out);
}

// round 17
// speedup vs baseline: 1.0441x; 1.0346x over previous
#include <cuda_runtime.h>
#include <cuda_fp16.h>
#include <math.h>
#include <stdint.h>

// ---------------------------------------------------------------------------
// SpatialHead on sm_103a — fp16 mma + ldmatrix, halo-resident 3x3 convs.
// Fusions: offset conv + bilinear sampling in one kernel (offsets via smem);
// r2 conv + 1x1 conv + sigmoid in one kernel (cross-warp smem reduction).
// (R12 configuration — measured best.)
// ---------------------------------------------------------------------------

namespace sh {
constexpr int kB = 8, kH = 96, kW = 96;
constexpr int kPos = kB * kH * kW;          // 73728
constexpr float kEps = 1e-5f;
}

// ------------------------- scratch (__device__ globals) --------------------
__device__ __align__(16) __half g_feath[(size_t)sh::kPos * 256];
__device__ __align__(16) __half g_buf0h[sh::kPos * 64];
__device__ __align__(16) __half g_buf1h[sh::kPos * 64];
__device__ __align__(16) __half g_samph[(size_t)sh::kPos * 576];
__device__ __align__(16) __half g_w1h[64 * 2304];                 // [o][k]
__device__ __align__(16) __half g_woffh[32 * 576];
__device__ __align__(16) __half g_wdch[64 * 576];
__device__ __align__(16) __half g_wr1h[64 * 576];
__device__ __align__(16) __half g_wr2h[64 * 576];
__device__ __align__(16) float  g_cb[sh::kH * sh::kW * 64];
__device__ float g_bnsc[4 * 64];
__device__ float g_bnsh[4 * 64];

// ------------------------------ helpers ------------------------------------
__device__ __forceinline__ unsigned smem_u32(const void* p) {
    unsigned a;
    asm("{ .reg .u64 t; cvta.to.shared.u64 t, %1; cvt.u32.u64 %0, t; }"
        : "=r"(a) : "l"(p));
    return a;
}
__device__ __forceinline__ void cp_async16(unsigned dst, const void* src, bool ok) {
    int sz = ok ? 16 : 0;
    asm volatile("cp.async.cg.shared.global [%0], [%1], 16, %2;\n"
                 :: "r"(dst), "l"(src), "r"(sz));
}
__device__ __forceinline__ void cp_commit() {
    asm volatile("cp.async.commit_group;\n");
}
template <int N>
__device__ __forceinline__ void cp_wait() {
    asm volatile("cp.async.wait_group %0;\n" :: "n"(N));
}
__device__ __forceinline__ void ldsm_x4(uint32_t r[4], unsigned addr) {
    asm volatile("ldmatrix.sync.aligned.m8n8.x4.shared.b16 {%0,%1,%2,%3}, [%4];"
                 : "=r"(r[0]), "=r"(r[1]), "=r"(r[2]), "=r"(r[3]) : "r"(addr));
}
__device__ __forceinline__ void mma_f16(float c[4], const uint32_t a[4],
                                        uint32_t b0, uint32_t b1) {
    asm volatile(
        "mma.sync.aligned.m16n8k16.row.col.f32.f16.f16.f32 "
        "{%0,%1,%2,%3}, {%4,%5,%6,%7}, {%8,%9}, {%0,%1,%2,%3};\n"
        : "+f"(c[0]), "+f"(c[1]), "+f"(c[2]), "+f"(c[3])
        : "r"(a[0]), "r"(a[1]), "r"(a[2]), "r"(a[3]), "r"(b0), "r"(b1));
}
__device__ __forceinline__ uint32_t packh2(float a, float b) {
    __half2 p = __floats2half2_rn(a, b);
    return *(uint32_t*)&p;
}

// ------------------------------ prep kernel (incl. f2h) --------------------
__global__ void prep_kernel(
    const float* __restrict__ features,
    const float* __restrict__ coord_w, const float* __restrict__ coord_b,
    const float* __restrict__ off_w, const float* __restrict__ dc_w,
    const float* __restrict__ r1_w, const float* __restrict__ r2_w,
    const float* __restrict__ bn1g, const float* __restrict__ bn1b,
    const float* __restrict__ bn1m, const float* __restrict__ bn1v,
    const float* __restrict__ bn2g, const float* __restrict__ bn2b,
    const float* __restrict__ bn2m, const float* __restrict__ bn2v,
    const float* __restrict__ bn3g, const float* __restrict__ bn3b,
    const float* __restrict__ bn3m, const float* __restrict__ bn3v,
    const float* __restrict__ bn4g, const float* __restrict__ bn4b,
    const float* __restrict__ bn4m, const float* __restrict__ bn4v)
{
    int idx = blockIdx.x * blockDim.x + threadIdx.x;
    const int NF = sh::kPos * 32;
    const int N1 = 64 * 2304;
    const int N2 = sh::kH * sh::kW * 64;
    const int NOFF = 32 * 576;
    const int N3 = 64 * 576;

    if (idx < NF) {
        const float4* s = (const float4*)features + (size_t)idx * 2;
        float4 v0 = s[0], v1 = s[1];
        uint4 h;
        h.x = packh2(v0.x, v0.y); h.y = packh2(v0.z, v0.w);
        h.z = packh2(v1.x, v1.y); h.w = packh2(v1.z, v1.w);
        *(uint4*)&g_feath[(size_t)idx * 8] = h;
        return;
    }
    idx -= NF;
    if (idx < N1) {
        int o = idx / 2304, k = idx % 2304;
        int t = k >> 8, c = k & 255;
        g_w1h[idx] = __float2half(coord_w[(o * 258 + c) * 9 + t]);
        return;
    }
    idx -= N1;
    if (idx < N2) {
        int o = idx & 63, p = idx >> 6;
        int y = p / 96, x = p % 96;
        float acc = coord_b[o];
        #pragma unroll
        for (int t = 0; t < 9; t++) {
            int yy = y + t / 3 - 1, xx = x + t % 3 - 1;
            if ((unsigned)yy < 96u && (unsigned)xx < 96u) {
                float xv = fmaf((float)xx, 2.0f / 95.0f, -1.0f);
                float yv = fmaf((float)yy, 2.0f / 95.0f, -1.0f);
                acc = fmaf(coord_w[(o * 258 + 256) * 9 + t], xv, acc);
                acc = fmaf(coord_w[(o * 258 + 257) * 9 + t], yv, acc);
            }
        }
        g_cb[p * 64 + o] = acc;
        return;
    }
    idx -= N2;
    if (idx < NOFF) {
        int o = idx / 576, k = idx % 576;
        int t = k >> 6, c = k & 63;
        g_woffh[idx] = (o < 18) ? __float2half(off_w[(o * 64 + c) * 9 + t])
                                : __float2half(0.0f);
        return;
    }
    idx -= NOFF;
    if (idx < N3) {
        int o = idx / 576, k = idx % 576;
        int t = k >> 6, c = k & 63;
        g_wdch[idx] = __float2half(dc_w[(o * 64 + c) * 9 + t]);
        return;
    }
    idx -= N3;
    if (idx < N3) {
        int o = idx / 576, k = idx % 576;
        int t = k >> 6, c = k & 63;
        g_wr1h[idx] = __float2half(r1_w[(o * 64 + c) * 9 + t]);
        return;
    }
    idx -= N3;
    if (idx < N3) {
        int o = idx / 576, k = idx % 576;
        int t = k >> 6, c = k & 63;
        g_wr2h[idx] = __float2half(r2_w[(o * 64 + c) * 9 + t]);
        return;
    }
    idx -= N3;
    if (idx < 512) {
        int which = idx >> 7, r = idx & 127, o = r & 63;
        const float* gs; const float* bs; const float* ms; const float* vs;
        if (which == 0)      { gs = bn1g; bs = bn1b; ms = bn1m; vs = bn1v; }
        else if (which == 1) { gs = bn2g; bs = bn2b; ms = bn2m; vs = bn2v; }
        else if (which == 2) { gs = bn3g; bs = bn3b; ms = bn3m; vs = bn3v; }
        else                 { gs = bn4g; bs = bn4b; ms = bn4m; vs = bn4v; }
        float sc = gs[o] * rsqrtf(vs[o] + sh::kEps);
        if (r < 64) g_bnsc[which * 64 + o] = sc;
        else        g_bnsh[which * 64 + o] = bs[o] - ms[o] * sc;
    }
}

// ------------------- 3x3 conv with smem-resident halo tile -----------------
constexpr int HPITCH = 72;                  // halves per halo position
constexpr int HROWS = 6 * 34;               // 204
constexpr int HBYTES = HROWS * HPITCH * 2;  // 29376
constexpr int BPITCH = 40;                  // halves per weight row

template <int CIN, int BN, int MODE>
__global__ void __launch_bounds__(256, 4)
conv3x3_halo(const __half* __restrict__ in, const __half* __restrict__ wT,
             const float* __restrict__ posbias,
             const float* __restrict__ bnsc, const float* __restrict__ bnsh,
             __half* __restrict__ out)
{
    constexpr int NGRP = CIN / 64;
    constexpr int KTOT = 9 * CIN;
    constexpr int BSTG = BN * BPITCH;
    constexpr int NWARP = BN / 2;
    constexpr int NBT = NWARP / 8;
    extern __shared__ __half smemh[];
    const unsigned hBase = smem_u32(smemh);
    const unsigned bBase = hBase + HBYTES;

    const int tid = threadIdx.x;
    const int wid = tid >> 5;
    const int lane = tid & 31;
    const int warpM = wid & 3;
    const int warpN = wid >> 2;
    const int g = lane >> 2;
    const int tg = lane & 3;

    const int x0 = blockIdx.x * 32;
    const int ybase = blockIdx.y * 4;
    const int b = blockIdx.z;

    const int lrow = lane & 7;
    const int lsel = lane >> 3;

    unsigned aAddrBase[2];
    #pragma unroll
    for (int mt = 0; mt < 2; mt++) {
        const int p = warpM * 32 + mt * 16 + lrow + ((lsel & 1) << 3);
        const int py = p >> 5, px = p & 31;
        aAddrBase[mt] = hBase
            + (unsigned)(((py + 1) * 34 + (px + 1)) * HPITCH
                         + ((lsel >> 1) << 3)) * 2u;
    }
    const int boff = (warpN * NWARP + lrow + ((lsel >> 1) << 3)) * BPITCH
                   + ((lsel & 1) << 3);

    float c[2][NBT][4];
    #pragma unroll
    for (int mt = 0; mt < 2; mt++)
        #pragma unroll
        for (int nt = 0; nt < NBT; nt++)
            #pragma unroll
            for (int r = 0; r < 4; r++) c[mt][nt][r] = 0.0f;

    auto prefetchB = [&](int grp, int ch, int buf) {
        if (tid < BN * 4) {
            const int o = tid >> 2;
            const int q = tid & 3;
            const int koff = (ch >> 1) * CIN + grp * 64 + (ch & 1) * 32;
            const __half* ws = wT + (size_t)o * KTOT + koff + q * 8;
            unsigned dstB = bBase + (unsigned)(buf * BSTG + o * BPITCH) * 2u
                          + q * 16u;
            cp_async16(dstB, ws, true);
        }
    };

    for (int grp = 0; grp < NGRP; grp++) {
        __syncthreads();
        if (tid < HROWS) {
            const int hr = tid / 34, hc = tid % 34;
            const int yy = ybase - 1 + hr, xx = x0 - 1 + hc;
            const bool ok = ((unsigned)yy < 96u) && ((unsigned)xx < 96u);
            const __half* src = ok
                ? in + (size_t)((b * 96 + yy) * 96 + xx) * CIN + grp * 64
                : in;
            unsigned dst = hBase + (unsigned)(tid * HPITCH) * 2u;
            #pragma unroll
            for (int q = 0; q < 8; q++)
                cp_async16(dst + q * 16, src + q * 8, ok);
        }
        cp_commit();
        prefetchB(grp, 0, 0); cp_commit();
        prefetchB(grp, 1, 1); cp_commit();

        #pragma unroll
        for (int ch = 0; ch < 18; ch++) {
            cp_wait<1>();
            __syncthreads();
            if (ch + 2 < 18) prefetchB(grp, ch + 2, (ch + 2) % 3);
            cp_commit();

            const int t = ch >> 1;
            const int dy = t / 3 - 1, dx = t % 3 - 1;
            const int aoffc = (dy * 34 + dx) * (HPITCH * 2) + (ch & 1) * 64;
            const unsigned bAddr = bBase
                + (unsigned)((ch % 3) * BSTG + boff) * 2u;

            #pragma unroll
            for (int ks = 0; ks < 2; ks++) {
                uint32_t a[2][4], bb[NBT / 2][4];
                ldsm_x4(a[0], aAddrBase[0] + aoffc + ks * 32);
                ldsm_x4(a[1], aAddrBase[1] + aoffc + ks * 32);
                #pragma unroll
                for (int p = 0; p < NBT / 2; p++)
                    ldsm_x4(bb[p], bAddr + p * 16 * BPITCH * 2 + ks * 32);
                #pragma unroll
                for (int p = 0; p < NBT / 2; p++)
                    #pragma unroll
                    for (int q = 0; q < 2; q++) {
                        const int nt = p * 2 + q;
                        mma_f16(c[0][nt], a[0], bb[p][2 * q], bb[p][2 * q + 1]);
                        mma_f16(c[1][nt], a[1], bb[p][2 * q], bb[p][2 * q + 1]);
                    }
            }
        }
    }

    #pragma unroll
    for (int mt = 0; mt < 2; mt++) {
        #pragma unroll
        for (int rr = 0; rr < 2; rr++) {
            const int m = warpM * 32 + mt * 16 + rr * 8 + g;
            const int py = ybase + (m >> 5);
            const int px = x0 + (m & 31);
            const size_t pos = ((size_t)b * 96 + py) * 96 + px;
            #pragma unroll
            for (int nt = 0; nt < NBT; nt++) {
                const int o = warpN * NWARP + nt * 8 + tg * 2;
                float v0 = c[mt][nt][rr * 2 + 0];
                float v1 = c[mt][nt][rr * 2 + 1];
                if constexpr (MODE == 0) {
                    const float2 pb = *(const float2*)&posbias[(size_t)(py * 96 + px) * 64 + o];
                    v0 += pb.x; v1 += pb.y;
                }
                const float2 sc = *(const float2*)&bnsc[o];
                const float2 shb = *(const float2*)&bnsh[o];
                v0 = fmaxf(fmaf(v0, sc.x, shb.x), 0.0f);
                v1 = fmaxf(fmaf(v1, sc.y, shb.y), 0.0f);
                *(__half2*)&out[pos * 64 + o] = __floats2half2_rn(v0, v1);
            }
        }
    }
}

// --------------- fused offset conv (64->18) + bilinear sampling ------------
__global__ void __launch_bounds__(256, 4)
offset_sample(const __half* __restrict__ in, const __half* __restrict__ wT,
              const float* __restrict__ chbias, __half* __restrict__ samp)
{
    constexpr int BN = 32;
    constexpr int KTOT = 576;
    constexpr int BSTG = BN * BPITCH;
    __shared__ float sOff[128 * 18];
    extern __shared__ __half smemh[];
    const unsigned hBase = smem_u32(smemh);
    const unsigned bBase = hBase + HBYTES;

    const int tid = threadIdx.x;
    const int wid = tid >> 5;
    const int lane = tid & 31;
    const int warpM = wid & 3;
    const int warpN = wid >> 2;
    const int g = lane >> 2;
    const int tg = lane & 3;

    const int x0 = blockIdx.x * 32;
    const int ybase = blockIdx.y * 4;
    const int b = blockIdx.z;

    const int lrow = lane & 7;
    const int lsel = lane >> 3;

    unsigned aAddrBase[2];
    #pragma unroll
    for (int mt = 0; mt < 2; mt++) {
        const int p = warpM * 32 + mt * 16 + lrow + ((lsel & 1) << 3);
        const int py = p >> 5, px = p & 31;
        aAddrBase[mt] = hBase
            + (unsigned)(((py + 1) * 34 + (px + 1)) * HPITCH
                         + ((lsel >> 1) << 3)) * 2u;
    }
    const int boff = (warpN * 16 + lrow + ((lsel >> 1) << 3)) * BPITCH
                   + ((lsel & 1) << 3);

    float c[2][2][4];
    #pragma unroll
    for (int mt = 0; mt < 2; mt++)
        #pragma unroll
        for (int nt = 0; nt < 2; nt++)
            #pragma unroll
            for (int r = 0; r < 4; r++) c[mt][nt][r] = 0.0f;

    auto prefetchB = [&](int ch, int buf) {
        if (tid < BN * 4) {
            const int o = tid >> 2;
            const int q = tid & 3;
            const int koff = (ch >> 1) * 64 + (ch & 1) * 32;
            const __half* ws = wT + (size_t)o * KTOT + koff + q * 8;
            unsigned dstB = bBase + (unsigned)(buf * BSTG + o * BPITCH) * 2u
                          + q * 16u;
            cp_async16(dstB, ws, true);
        }
    };

    if (tid < HROWS) {
        const int hr = tid / 34, hc = tid % 34;
        const int yy = ybase - 1 + hr, xx = x0 - 1 + hc;
        const bool ok = ((unsigned)yy < 96u) && ((unsigned)xx < 96u);
        const __half* src = ok
            ? in + (size_t)((b * 96 + yy) * 96 + xx) * 64
            : in;
        unsigned dst = hBase + (unsigned)(tid * HPITCH) * 2u;
        #pragma unroll
        for (int q = 0; q < 8; q++)
            cp_async16(dst + q * 16, src + q * 8, ok);
    }
    cp_commit();
    prefetchB(0, 0); cp_commit();
    prefetchB(1, 1); cp_commit();

    #pragma unroll
    for (int ch = 0; ch < 18; ch++) {
        cp_wait<1>();
        __syncthreads();
        if (ch + 2 < 18) prefetchB(ch + 2, (ch + 2) % 3);
        cp_commit();

        const int t = ch >> 1;
        const int dy = t / 3 - 1, dx = t % 3 - 1;
        const int aoffc = (dy * 34 + dx) * (HPITCH * 2) + (ch & 1) * 64;
        const unsigned bAddr = bBase + (unsigned)((ch % 3) * BSTG + boff) * 2u;

        #pragma unroll
        for (int ks = 0; ks < 2; ks++) {
            uint32_t a[2][4], bb[4];
            ldsm_x4(a[0], aAddrBase[0] + aoffc + ks * 32);
            ldsm_x4(a[1], aAddrBase[1] + aoffc + ks * 32);
            ldsm_x4(bb, bAddr + ks * 32);
            #pragma unroll
            for (int q = 0; q < 2; q++) {
                mma_f16(c[0][q], a[0], bb[2 * q], bb[2 * q + 1]);
                mma_f16(c[1][q], a[1], bb[2 * q], bb[2 * q + 1]);
            }
        }
    }

    // epilogue -> offsets into smem
    #pragma unroll
    for (int mt = 0; mt < 2; mt++) {
        #pragma unroll
        for (int rr = 0; rr < 2; rr++) {
            const int m = warpM * 32 + mt * 16 + rr * 8 + g;
            #pragma unroll
            for (int nt = 0; nt < 2; nt++) {
                const int o = warpN * 16 + nt * 8 + tg * 2;
                if (o < 18)
                    sOff[m * 18 + o] = c[mt][nt][rr * 2 + 0] + chbias[o];
                if (o + 1 < 18)
                    sOff[m * 18 + o + 1] = c[mt][nt][rr * 2 + 1] + chbias[o + 1];
            }
        }
    }
    __syncthreads();

    // sampling phase: 128 pos x 8 channel-quarters, 4 units per thread
    const uint4* img = (const uint4*)(in + (size_t)b * (96 * 96 * 64));
    #pragma unroll 1
    for (int u = 0; u < 4; u++) {
        const int unit = u * 256 + tid;
        const int lp = unit >> 3;
        const int cq = unit & 7;
        const int py = ybase + (lp >> 5);
        const int px = x0 + (lp & 31);
        const size_t gpos = ((size_t)b * 96 + py) * 96 + px;
        uint4* outp = (uint4*)(samp + gpos * 576);
        #pragma unroll
        for (int t = 0; t < 9; t++) {
            const float oy = sOff[lp * 18 + 2 * t];
            const float ox = sOff[lp * 18 + 2 * t + 1];
            const float pyf = (float)(py + t / 3 - 1) + oy;
            const float pxf = (float)(px + t % 3 - 1) + ox;
            const float y0f = floorf(pyf), x0f = floorf(pxf);
            const float fy = pyf - y0f, fx = pxf - x0f;
            const int iy = (int)y0f, ix = (int)x0f;
            const float w00 = (1.0f - fy) * (1.0f - fx);
            const float w01 = (1.0f - fy) * fx;
            const float w10 = fy * (1.0f - fx);
            const float w11 = fy * fx;
            float2 acc[4] = {{0.f,0.f},{0.f,0.f},{0.f,0.f},{0.f,0.f}};
            auto corner = [&](int yy, int xx, float w) {
                if ((unsigned)yy < 96u && (unsigned)xx < 96u) {
                    uint4 v = img[(yy * 96 + xx) * 8 + cq];
                    const __half2* hp = (const __half2*)&v;
                    #pragma unroll
                    for (int i = 0; i < 4; i++) {
                        float2 f = __half22float2(hp[i]);
                        acc[i].x = fmaf(w, f.x, acc[i].x);
                        acc[i].y = fmaf(w, f.y, acc[i].y);
                    }
                }
            };
            corner(iy,     ix,     w00);
            corner(iy,     ix + 1, w01);
            corner(iy + 1, ix,     w10);
            corner(iy + 1, ix + 1, w11);
            __half2 r[4];
            #pragma unroll
            for (int i = 0; i < 4; i++)
                r[i] = __floats2half2_rn(acc[i].x, acc[i].y);
            outp[t * 8 + cq] = *(uint4*)r;
        }
    }
}

// ---------------- fused r2 conv + BN4 + ReLU + 1x1 conv + sigmoid ----------
__global__ void __launch_bounds__(256, 4)
r2_final(const __half* __restrict__ in, const __half* __restrict__ wT,
         const float* __restrict__ bnsc, const float* __restrict__ bnsh,
         const float* __restrict__ ow, const float* __restrict__ ob,
         float* __restrict__ out)
{
    constexpr int BN = 64;
    constexpr int KTOT = 576;
    constexpr int BSTG = BN * BPITCH;
    __shared__ float sRed[2][128];
    extern __shared__ __half smemh[];
    const unsigned hBase = smem_u32(smemh);
    const unsigned bBase = hBase + HBYTES;

    const int tid = threadIdx.x;
    const int wid = tid >> 5;
    const int lane = tid & 31;
    const int warpM = wid & 3;
    const int warpN = wid >> 2;
    const int g = lane >> 2;
    const int tg = lane & 3;

    const int x0 = blockIdx.x * 32;
    const int ybase = blockIdx.y * 4;
    const int b = blockIdx.z;

    const int lrow = lane & 7;
    const int lsel = lane >> 3;

    unsigned aAddrBase[2];
    #pragma unroll
    for (int mt = 0; mt < 2; mt++) {
        const int p = warpM * 32 + mt * 16 + lrow + ((lsel & 1) << 3);
        const int py = p >> 5, px = p & 31;
        aAddrBase[mt] = hBase
            + (unsigned)(((py + 1) * 34 + (px + 1)) * HPITCH
                         + ((lsel >> 1) << 3)) * 2u;
    }
    const int boff = (warpN * 32 + lrow + ((lsel >> 1) << 3)) * BPITCH
                   + ((lsel & 1) << 3);

    float c[2][4][4];
    #pragma unroll
    for (int mt = 0; mt < 2; mt++)
        #pragma unroll
        for (int nt = 0; nt < 4; nt++)
            #pragma unroll
            for (int r = 0; r < 4; r++) c[mt][nt][r] = 0.0f;

    auto prefetchB = [&](int ch, int buf) {
        const int o = tid >> 2;
        const int q = tid & 3;
        const int koff = (ch >> 1) * 64 + (ch & 1) * 32;
        const __half* ws = wT + (size_t)o * KTOT + koff + q * 8;
        unsigned dstB = bBase + (unsigned)(buf * BSTG + o * BPITCH) * 2u
                      + q * 16u;
        cp_async16(dstB, ws, true);
    };

    if (tid < HROWS) {
        const int hr = tid / 34, hc = tid % 34;
        const int yy = ybase - 1 + hr, xx = x0 - 1 + hc;
        const bool ok = ((unsigned)yy < 96u) && ((unsigned)xx < 96u);
        const __half* src = ok
            ? in + (size_t)((b * 96 + yy) * 96 + xx) * 64
            : in;
        unsigned dst = hBase + (unsigned)(tid * HPITCH) * 2u;
        #pragma unroll
        for (int q = 0; q < 8; q++)
            cp_async16(dst + q * 16, src + q * 8, ok);
    }
    cp_commit();
    prefetchB(0, 0); cp_commit();
    prefetchB(1, 1); cp_commit();

    #pragma unroll
    for (int ch = 0; ch < 18; ch++) {
        cp_wait<1>();
        __syncthreads();
        if (ch + 2 < 18) prefetchB(ch + 2, (ch + 2) % 3);
        cp_commit();

        const int t = ch >> 1;
        const int dy = t / 3 - 1, dx = t % 3 - 1;
        const int aoffc = (dy * 34 + dx) * (HPITCH * 2) + (ch & 1) * 64;
        const unsigned bAddr = bBase + (unsigned)((ch % 3) * BSTG + boff) * 2u;

        #pragma unroll
        for (int ks = 0; ks < 2; ks++) {
            uint32_t a[2][4], bb[2][4];
            ldsm_x4(a[0], aAddrBase[0] + aoffc + ks * 32);
            ldsm_x4(a[1], aAddrBase[1] + aoffc + ks * 32);
            ldsm_x4(bb[0], bAddr + ks * 32);
            ldsm_x4(bb[1], bAddr + 16 * BPITCH * 2 + ks * 32);
            #pragma unroll
            for (int p = 0; p < 2; p++)
                #pragma unroll
                for (int q = 0; q < 2; q++) {
                    const int nt = p * 2 + q;
                    mma_f16(c[0][nt], a[0], bb[p][2 * q], bb[p][2 * q + 1]);
                    mma_f16(c[1][nt], a[1], bb[p][2 * q], bb[p][2 * q + 1]);
                }
        }
    }

    float part[4] = {0.f, 0.f, 0.f, 0.f};
    #pragma unroll
    for (int mt = 0; mt < 2; mt++) {
        #pragma unroll
        for (int rr = 0; rr < 2; rr++) {
            #pragma unroll
            for (int nt = 0; nt < 4; nt++) {
                const int o = warpN * 32 + nt * 8 + tg * 2;
                const float2 sc = *(const float2*)&bnsc[o];
                const float2 shb = *(const float2*)&bnsh[o];
                float v0 = fmaxf(fmaf(c[mt][nt][rr * 2 + 0], sc.x, shb.x), 0.0f);
                float v1 = fmaxf(fmaf(c[mt][nt][rr * 2 + 1], sc.y, shb.y), 0.0f);
                part[mt * 2 + rr] = fmaf(v0, ow[o],
                                    fmaf(v1, ow[o + 1], part[mt * 2 + rr]));
            }
        }
    }
    #pragma unroll
    for (int i = 0; i < 4; i++) {
        part[i] += __shfl_xor_sync(0xffffffffu, part[i], 1);
        part[i] += __shfl_xor_sync(0xffffffffu, part[i], 2);
    }
    if (tg == 0) {
        #pragma unroll
        for (int i = 0; i < 4; i++) {
            const int m = warpM * 32 + (i >> 1) * 16 + (i & 1) * 8 + g;
            sRed[warpN][m] = part[i];
        }
    }
    __syncthreads();
    if (tid < 128) {
        const int py = ybase + (tid >> 5);
        const int px = x0 + (tid & 31);
        const float s = sRed[0][tid] + sRed[1][tid] + ob[0];
        out[((size_t)b * 96 + py) * 96 + px] = 1.0f / (1.0f + expf(-s));
    }
}

// ------------------- streaming GEMM for deform einsum ----------------------
constexpr int STAGES = 3;
constexpr int PITCH = 40;
constexpr int ABUF_H = 128 * PITCH;

__global__ void __launch_bounds__(256, 4)
einsum_mma(const __half* __restrict__ in, const __half* __restrict__ wT,
           const float* __restrict__ bnsc, const float* __restrict__ bnsh,
           __half* __restrict__ out)
{
    constexpr int CIN = 576;
    constexpr int KCH = CIN / 32;
    constexpr int BBUF_H = 64 * PITCH;
    extern __shared__ __half smemh[];
    const unsigned aBase = smem_u32(smemh);
    const unsigned bBase = aBase + STAGES * ABUF_H * 2;

    const int tid = threadIdx.x;
    const int wid = tid >> 5;
    const int lane = tid & 31;
    const int warpM = wid & 3;
    const int warpN = wid >> 2;
    const int g = lane >> 2;
    const int tg = lane & 3;

    const int x0 = blockIdx.x * 32;
    const int ybase = blockIdx.y * 4;
    const int b = blockIdx.z;

    const int lrow = lane & 7;
    const int lsel = lane >> 3;
    const int aoff = (warpM * 32 + lrow + ((lsel & 1) << 3)) * PITCH
                   + ((lsel >> 1) << 3);
    const int boff = (warpN * 32 + lrow + ((lsel >> 1) << 3)) * PITCH
                   + ((lsel & 1) << 3);

    const int fp = tid >> 1;
    const int fhalf = (tid & 1) * 16;
    const int fpy = fp >> 5, fpx = fp & 31;

    float c[2][4][4];
    #pragma unroll
    for (int mt = 0; mt < 2; mt++)
        #pragma unroll
        for (int nt = 0; nt < 4; nt++)
            #pragma unroll
            for (int r = 0; r < 4; r++) c[mt][nt][r] = 0.0f;

    auto prefetch = [&](int ch) {
        const int s = ch % STAGES;
        const int c0 = ch * 32;
        const int yy = ybase + fpy;
        const int xx = x0 + fpx;
        const __half* src = in + (size_t)((b * 96 + yy) * 96 + xx) * CIN + c0 + fhalf;
        unsigned dstA = aBase + (unsigned)(s * ABUF_H + fp * PITCH + fhalf) * 2u;
        cp_async16(dstA, src, true);
        cp_async16(dstA + 16, src + 8, true);
        const int o = tid >> 2;
        const int q = tid & 3;
        const __half* ws = wT + (size_t)o * CIN + ch * 32 + q * 8;
        unsigned dstB = bBase + (unsigned)(s * BBUF_H + o * PITCH) * 2u + q * 16u;
        cp_async16(dstB, ws, true);
    };

    #pragma unroll
    for (int i = 0; i < STAGES - 1; i++) {
        prefetch(i);
        cp_commit();
    }

    for (int ch = 0; ch < KCH; ch++) {
        cp_wait<STAGES - 2>();
        __syncthreads();

        if (ch + STAGES - 1 < KCH) prefetch(ch + STAGES - 1);
        cp_commit();

        const int s = ch % STAGES;
        const unsigned aAddr = aBase + (unsigned)(s * ABUF_H + aoff) * 2u;
        const unsigned bAddr = bBase + (unsigned)(s * BBUF_H + boff) * 2u;

        #pragma unroll
        for (int ks = 0; ks < 2; ks++) {
            uint32_t a[2][4], bb[2][4];
            ldsm_x4(a[0], aAddr + ks * 32);
            ldsm_x4(a[1], aAddr + 16 * PITCH * 2 + ks * 32);
            ldsm_x4(bb[0], bAddr + ks * 32);
            ldsm_x4(bb[1], bAddr + 16 * PITCH * 2 + ks * 32);
            #pragma unroll
            for (int p = 0; p < 2; p++)
                #pragma unroll
                for (int q = 0; q < 2; q++) {
                    const int nt = p * 2 + q;
                    mma_f16(c[0][nt], a[0], bb[p][2 * q], bb[p][2 * q + 1]);
                    mma_f16(c[1][nt], a[1], bb[p][2 * q], bb[p][2 * q + 1]);
                }
        }
    }

    #pragma unroll
    for (int mt = 0; mt < 2; mt++) {
        #pragma unroll
        for (int rr = 0; rr < 2; rr++) {
            const int m = warpM * 32 + mt * 16 + rr * 8 + g;
            const int py = ybase + (m >> 5);
            const int px = x0 + (m & 31);
            const size_t pos = ((size_t)b * 96 + py) * 96 + px;
            #pragma unroll
            for (int nt = 0; nt < 4; nt++) {
                const int o = warpN * 32 + nt * 8 + tg * 2;
                float v0 = c[mt][nt][rr * 2 + 0];
                float v1 = c[mt][nt][rr * 2 + 1];
                const float2 sc = *(const float2*)&bnsc[o];
                const float2 shb = *(const float2*)&bnsh[o];
                v0 = fmaxf(fmaf(v0, sc.x, shb.x), 0.0f);
                v1 = fmaxf(fmaf(v1, sc.y, shb.y), 0.0f);
                *(__half2*)&out[pos * 64 + o] = __floats2half2_rn(v0, v1);
            }
        }
    }
}

// ------------------------------ launcher -----------------------------------
extern "C" void kernel_launch(void* const* d_in, const int* in_sizes, int n_in,
                              void* d_out, int out_size)
{
    const float* features = (const float*)d_in[0];
    const float* coord_w  = (const float*)d_in[1];
    const float* coord_b  = (const float*)d_in[2];
    const float* bn1g = (const float*)d_in[3];
    const float* bn1b = (const float*)d_in[4];
    const float* bn1m = (const float*)d_in[5];
    const float* bn1v = (const float*)d_in[6];
    const float* off_w = (const float*)d_in[7];
    const float* off_b = (const float*)d_in[8];
    const float* dc_w  = (const float*)d_in[9];
    const float* bn2g = (const float*)d_in[10];
    const float* bn2b = (const float*)d_in[11];
    const float* bn2m = (const float*)d_in[12];
    const float* bn2v = (const float*)d_in[13];
    const float* r1_w = (const float*)d_in[14];
    const float* bn3g = (const float*)d_in[15];
    const float* bn3b = (const float*)d_in[16];
    const float* bn3m = (const float*)d_in[17];
    const float* bn3v = (const float*)d_in[18];
    const float* r2_w = (const float*)d_in[19];
    const float* bn4g = (const float*)d_in[20];
    const float* bn4b = (const float*)d_in[21];
    const float* bn4m = (const float*)d_in[22];
    const float* bn4v = (const float*)d_in[23];
    const float* out_w = (const float*)d_in[24];
    const float* out_b = (const float*)d_in[25];

    __half *p_feath, *p_buf0, *p_buf1, *p_samp, *p_w1h, *p_woffh, *p_wdch,
           *p_wr1h, *p_wr2h;
    float *p_cb, *p_bnsc, *p_bnsh;
    cudaGetSymbolAddress((void**)&p_feath, g_feath);
    cudaGetSymbolAddress((void**)&p_buf0, g_buf0h);
    cudaGetSymbolAddress((void**)&p_buf1, g_buf1h);
    cudaGetSymbolAddress((void**)&p_samp, g_samph);
    cudaGetSymbolAddress((void**)&p_w1h,  g_w1h);
    cudaGetSymbolAddress((void**)&p_woffh, g_woffh);
    cudaGetSymbolAddress((void**)&p_wdch, g_wdch);
    cudaGetSymbolAddress((void**)&p_wr1h, g_wr1h);
    cudaGetSymbolAddress((void**)&p_wr2h, g_wr2h);
    cudaGetSymbolAddress((void**)&p_cb,   g_cb);
    cudaGetSymbolAddress((void**)&p_bnsc, g_bnsc);
    cudaGetSymbolAddress((void**)&p_bnsh, g_bnsh);

    constexpr int HSM64 = HBYTES + 3 * 64 * BPITCH * 2;   // 44736
    constexpr int HSM32 = HBYTES + 3 * 32 * BPITCH * 2;   // 37056
    constexpr int ESM   = STAGES * (ABUF_H + 64 * PITCH) * 2;  // 46080

    cudaFuncSetAttribute(conv3x3_halo<256, 64, 0>,
                         cudaFuncAttributeMaxDynamicSharedMemorySize, HSM64);
    cudaFuncSetAttribute(conv3x3_halo<64, 64, 2>,
                         cudaFuncAttributeMaxDynamicSharedMemorySize, HSM64);
    cudaFuncSetAttribute(offset_sample,
                         cudaFuncAttributeMaxDynamicSharedMemorySize, HSM32);
    cudaFuncSetAttribute(r2_final,
                         cudaFuncAttributeMaxDynamicSharedMemorySize, HSM64);
    cudaFuncSetAttribute(einsum_mma,
                         cudaFuncAttributeMaxDynamicSharedMemorySize, ESM);

    // 1. prep: f2h + weight repack + coord bias map + folded BN
    const int prep_total = sh::kPos * 32 + 64 * 2304 + 96 * 96 * 64
                         + 32 * 576 + 3 * 64 * 576 + 512;
    prep_kernel<<<(prep_total + 255) / 256, 256>>>(
        features, coord_w, coord_b, off_w, dc_w, r1_w, r2_w,
        bn1g, bn1b, bn1m, bn1v, bn2g, bn2b, bn2m, bn2v,
        bn3g, bn3b, bn3m, bn3v, bn4g, bn4b, bn4m, bn4v);

    dim3 grid(3, 24, 8);   // 32 x-cols, 4 rows -> 128 positions per block

    // 2. coord conv (256->64, 4 halo groups) + coord bias + BN1 + ReLU
    conv3x3_halo<256, 64, 0><<<grid, 256, HSM64>>>(
        p_feath, p_w1h, p_cb, p_bnsc + 0, p_bnsh + 0, p_buf0);

    // 3+4. offset conv (64->18) + bias + bilinear sampling -> g_samph
    offset_sample<<<grid, 256, HSM32>>>(p_buf0, p_woffh, off_b, p_samp);

    // 5. deform einsum (K=576, streaming) + BN2 + ReLU -> buf1
    einsum_mma<<<grid, 256, ESM>>>(
        p_samp, p_wdch, p_bnsc + 64, p_bnsh + 64, p_buf1);

    // 6. r1 conv + BN3 + ReLU -> buf0
    conv3x3_halo<64, 64, 2><<<grid, 256, HSM64>>>(
        p_buf1, p_wr1h, nullptr, p_bnsc + 128, p_bnsh + 128, p_buf0);

    // 7+8. r2 conv + BN4 + ReLU + 1x1 conv + sigmoid -> d_out
    r2_final<<<grid, 256, HSM64>>>(
        p_buf0, p_wr2h, p_bnsc + 192, p_bnsh + 192, out_w, out_b,
        (float*)d_out);
}